// round 8
// baseline (speedup 1.0000x reference)
#include <cuda_runtime.h>
#include <cuda_bf16.h>
#include <cstdint>

using bf16 = __nv_bfloat16;

#define B_  8
#define C_  512
#define T_  2048
#define CQ_ 64

// ---------------------------------------------------------------------------
// Device-global scratch
// ---------------------------------------------------------------------------
__device__ bf16  g_xb [B_ * C_ * T_];
__device__ bf16  g_wqb[CQ_ * C_];
__device__ bf16  g_wkb[CQ_ * C_];
__device__ bf16  g_wvb[C_ * C_];
__device__ bf16  g_qb [B_ * CQ_ * T_];
__device__ bf16  g_kb [B_ * CQ_ * T_];
__device__ bf16  g_vb [B_ * C_  * T_];
__device__ bf16  g_p  [(size_t)B_ * T_ * T_];
__device__ float g_rs [B_ * 16 * T_];
__device__ float g_inv[B_ * T_];

// ---------------------------------------------------------------------------
// PTX helpers
// ---------------------------------------------------------------------------
__device__ __forceinline__ uint32_t cvta_s(const void* p) {
    return (uint32_t)__cvta_generic_to_shared(p);
}
__device__ __forceinline__ void ldsm_x4(uint32_t* r, uint32_t a) {
    asm volatile("ldmatrix.sync.aligned.m8n8.x4.shared.b16 {%0,%1,%2,%3},[%4];"
                 : "=r"(r[0]), "=r"(r[1]), "=r"(r[2]), "=r"(r[3]) : "r"(a));
}
__device__ __forceinline__ void ldsm_x4t(uint32_t* r, uint32_t a) {
    asm volatile("ldmatrix.sync.aligned.m8n8.x4.trans.shared.b16 {%0,%1,%2,%3},[%4];"
                 : "=r"(r[0]), "=r"(r[1]), "=r"(r[2]), "=r"(r[3]) : "r"(a));
}
__device__ __forceinline__ void ldsm_x2t(uint32_t* r, uint32_t a) {
    asm volatile("ldmatrix.sync.aligned.m8n8.x2.trans.shared.b16 {%0,%1},[%2];"
                 : "=r"(r[0]), "=r"(r[1]) : "r"(a));
}
__device__ __forceinline__ void mma_bf16(float* c, const uint32_t* a, const uint32_t* b) {
    asm volatile("mma.sync.aligned.m16n8k16.row.col.f32.bf16.bf16.f32 "
                 "{%0,%1,%2,%3},{%4,%5,%6,%7},{%8,%9},{%0,%1,%2,%3};"
                 : "+f"(c[0]), "+f"(c[1]), "+f"(c[2]), "+f"(c[3])
                 : "r"(a[0]), "r"(a[1]), "r"(a[2]), "r"(a[3]), "r"(b[0]), "r"(b[1]));
}
__device__ __forceinline__ void cp16(uint32_t dst, const void* src) {
    asm volatile("cp.async.ca.shared.global [%0], [%1], 16;" :: "r"(dst), "l"(src));
}
#define CP_COMMIT() asm volatile("cp.async.commit_group;" ::: "memory")
#define CP_WAIT(n)  asm volatile("cp.async.wait_group %0;" :: "n"(n) : "memory")

// ---------------------------------------------------------------------------
// fp32 -> bf16 converts
// ---------------------------------------------------------------------------
__device__ __forceinline__ void cvt4(const float* in, bf16* out, int i) {
    float4 v = *reinterpret_cast<const float4*>(in + (size_t)i * 4);
    __nv_bfloat162 lo = __floats2bfloat162_rn(v.x, v.y);
    __nv_bfloat162 hi = __floats2bfloat162_rn(v.z, v.w);
    uint2 pk;
    pk.x = *reinterpret_cast<uint32_t*>(&lo);
    pk.y = *reinterpret_cast<uint32_t*>(&hi);
    *reinterpret_cast<uint2*>(out + (size_t)i * 4) = pk;
}
__global__ void f2b_kernel(const float* __restrict__ in, bf16* __restrict__ out, int n4) {
    int i = blockIdx.x * blockDim.x + threadIdx.x;
    if (i < n4) cvt4(in, out, i);
}
__global__ void f2b_w(const float* __restrict__ a, bf16* __restrict__ ao, int na4,
                      const float* __restrict__ b, bf16* __restrict__ bo, int nb4,
                      const float* __restrict__ c, bf16* __restrict__ co, int nc4) {
    int i = blockIdx.x * blockDim.x + threadIdx.x;
    if (i < na4)                    cvt4(a, ao, i);
    else if (i < na4 + nb4)         cvt4(b, bo, i - na4);
    else if (i < na4 + nb4 + nc4)   cvt4(c, co, i - na4 - nb4);
}

// ---------------------------------------------------------------------------
// Fused projections (validated): blockIdx.y: 0=q, 1=k, 2..9=v tiles.
// ---------------------------------------------------------------------------
__global__ void proj_all(const bf16* __restrict__ wq, const float* __restrict__ bq, bf16* __restrict__ q,
                         const bf16* __restrict__ wk, const float* __restrict__ bk, bf16* __restrict__ k,
                         const bf16* __restrict__ wv, const float* __restrict__ bv, bf16* __restrict__ v,
                         const bf16* __restrict__ X)
{
    __shared__ bf16 sA[64][72];
    __shared__ bf16 sB[64][136];

    const int y = blockIdx.y;
    const bf16* W; const float* bias; bf16* Out; int m0; int Mrows;
    if (y == 0)      { W = wq; bias = bq; Out = q; m0 = 0;            Mrows = CQ_; }
    else if (y == 1) { W = wk; bias = bk; Out = k; m0 = 0;            Mrows = CQ_; }
    else             { W = wv; bias = bv; Out = v; m0 = (y - 2) * 64; Mrows = C_;  }

    const int b  = blockIdx.z;
    const int n0 = blockIdx.x * 128;
    const bf16* Xb = X + (size_t)b * C_ * T_;
    bf16*       Ob = Out + (size_t)b * Mrows * T_;

    const int tid  = threadIdx.x;
    const int lane = tid & 31;
    const int w    = tid >> 5;
    const int wm   = (w >> 2) * 32;
    const int wn   = (w & 3) * 32;

    float acc[2][4][4] = {};

    for (int kc = 0; kc < C_; kc += 64) {
        {
            int r = tid >> 3, c = (tid & 7) * 8;
            #pragma unroll
            for (int p = 0; p < 2; p++)
                *reinterpret_cast<uint4*>(&sA[r + p * 32][c]) =
                    *reinterpret_cast<const uint4*>(&W[(size_t)(m0 + r + p * 32) * C_ + kc + c]);
        }
        {
            int r = tid >> 4, c = (tid & 15) * 8;
            #pragma unroll
            for (int p = 0; p < 4; p++)
                *reinterpret_cast<uint4*>(&sB[r + p * 16][c]) =
                    *reinterpret_cast<const uint4*>(&Xb[(size_t)(kc + r + p * 16) * T_ + n0 + c]);
        }
        __syncthreads();

        #pragma unroll
        for (int kk = 0; kk < 64; kk += 16) {
            uint32_t af[2][4], bf_[4][2];
            #pragma unroll
            for (int mi = 0; mi < 2; mi++) {
                uint32_t a = cvta_s(&sA[wm + mi * 16 + (lane & 15)][kk + (lane >> 4) * 8]);
                ldsm_x4(af[mi], a);
            }
            #pragma unroll
            for (int ni = 0; ni < 4; ni++) {
                int r = kk + ((lane >> 3) & 1) * 8 + (lane & 7);
                uint32_t a = cvta_s(&sB[r][wn + ni * 8]);
                ldsm_x2t(bf_[ni], a);
            }
            #pragma unroll
            for (int mi = 0; mi < 2; mi++)
                #pragma unroll
                for (int ni = 0; ni < 4; ni++)
                    mma_bf16(acc[mi][ni], af[mi], bf_[ni]);
        }
        __syncthreads();
    }

    #pragma unroll
    for (int mi = 0; mi < 2; mi++) {
        int grow = m0 + wm + mi * 16 + (lane >> 2);
        float bv0 = bias[grow];
        float bv1 = bias[grow + 8];
        #pragma unroll
        for (int ni = 0; ni < 4; ni++) {
            int gcol = n0 + wn + ni * 8 + (lane & 3) * 2;
            __nv_bfloat162 v0 = __floats2bfloat162_rn(acc[mi][ni][0] + bv0, acc[mi][ni][1] + bv0);
            __nv_bfloat162 v1 = __floats2bfloat162_rn(acc[mi][ni][2] + bv1, acc[mi][ni][3] + bv1);
            *reinterpret_cast<__nv_bfloat162*>(&Ob[(size_t)grow * T_ + gcol]) = v0;
            *reinterpret_cast<__nv_bfloat162*>(&Ob[(size_t)(grow + 8) * T_ + gcol]) = v1;
        }
    }
}

// ---------------------------------------------------------------------------
// Scores + exp v3: 128x128 tile, 512 threads = 16 warps (4m x 4n),
// warp tile 32x32 (acc 32 regs -> high occupancy).
// ---------------------------------------------------------------------------
__global__ void __launch_bounds__(512, 2)
score_exp3(const bf16* __restrict__ Q, const bf16* __restrict__ Km,
           bf16* __restrict__ P, float* __restrict__ partial)
{
    __shared__ __align__(16) char sm[34816 + 2048];
    bf16*  sQ  = reinterpret_cast<bf16*>(sm);            // [64][136] (o, t)
    bf16*  sK  = reinterpret_cast<bf16*>(sm + 17408);    // [64][136] (o, s)
    bf16*  stg = reinterpret_cast<bf16*>(sm);            // [128][136] overlays Q/K
    float* red = reinterpret_cast<float*>(sm + 34816);   // [4][128]

    const int b  = blockIdx.z;
    const int s0 = blockIdx.x * 128;
    const int t0 = blockIdx.y * 128;
    const bf16* Qb = Q  + (size_t)b * CQ_ * T_;
    const bf16* Kb = Km + (size_t)b * CQ_ * T_;

    const int tid  = threadIdx.x;
    const int lane = tid & 31;
    const int w    = tid >> 5;
    const int wm   = (w >> 2) * 32;   // t warp offset
    const int wn   = (w & 3) * 32;    // s warp offset

    // load Q [64 o][128 t] and K [64 o][128 s]: 1024 uint4 each, 2/thread
    #pragma unroll
    for (int i = 0; i < 2; i++) {
        int u = tid + i * 512;
        int r = u >> 4, c = (u & 15) * 8;
        *reinterpret_cast<uint4*>(&sQ[r * 136 + c]) =
            *reinterpret_cast<const uint4*>(&Qb[(size_t)r * T_ + t0 + c]);
        *reinterpret_cast<uint4*>(&sK[r * 136 + c]) =
            *reinterpret_cast<const uint4*>(&Kb[(size_t)r * T_ + s0 + c]);
    }
    __syncthreads();

    float acc[2][4][4] = {};

    #pragma unroll
    for (int kk = 0; kk < 64; kk += 16) {
        uint32_t af[2][4], bf_[4][2];
        const int g = lane >> 3;
        #pragma unroll
        for (int mi = 0; mi < 2; mi++) {
            uint32_t a = cvta_s(&sQ[(kk + (g >> 1) * 8 + (lane & 7)) * 136 +
                                    wm + mi * 16 + (g & 1) * 8]);
            ldsm_x4t(af[mi], a);
        }
        #pragma unroll
        for (int p = 0; p < 2; p++) {
            uint32_t tmp[4];
            uint32_t a = cvta_s(&sK[(kk + ((lane >> 3) & 1) * 8 + (lane & 7)) * 136 +
                                    wn + p * 16 + (lane >> 4) * 8]);
            ldsm_x4t(tmp, a);
            bf_[2 * p][0] = tmp[0]; bf_[2 * p][1] = tmp[1];
            bf_[2 * p + 1][0] = tmp[2]; bf_[2 * p + 1][1] = tmp[3];
        }
        #pragma unroll
        for (int mi = 0; mi < 2; mi++)
            #pragma unroll
            for (int ni = 0; ni < 4; ni++)
                mma_bf16(acc[mi][ni], af[mi], bf_[ni]);
    }
    __syncthreads();   // done reading sQ/sK before stg overwrite

    // exp -> staged bf16 P + partial row sums
    float rs[2][2] = {};
    #pragma unroll
    for (int mi = 0; mi < 2; mi++) {
        int r0 = wm + mi * 16 + (lane >> 2);
        #pragma unroll
        for (int ni = 0; ni < 4; ni++) {
            float p0 = __expf(acc[mi][ni][0]);
            float p1 = __expf(acc[mi][ni][1]);
            float p2 = __expf(acc[mi][ni][2]);
            float p3 = __expf(acc[mi][ni][3]);
            rs[mi][0] += p0 + p1;
            rs[mi][1] += p2 + p3;
            int cc = wn + ni * 8 + (lane & 3) * 2;
            __nv_bfloat162 lo = __floats2bfloat162_rn(p0, p1);
            __nv_bfloat162 hi = __floats2bfloat162_rn(p2, p3);
            *reinterpret_cast<__nv_bfloat162*>(&stg[r0 * 136 + cc]) = lo;
            *reinterpret_cast<__nv_bfloat162*>(&stg[(r0 + 8) * 136 + cc]) = hi;
        }
    }
    // partial sums: reduce over lane&3, accumulate across n-warps in red
    // (4 n-warps write disjoint slots; each m-row covered once per n-warp)
    #pragma unroll
    for (int mi = 0; mi < 2; mi++)
        #pragma unroll
        for (int h = 0; h < 2; h++) {
            float v = rs[mi][h];
            v += __shfl_xor_sync(0xffffffffu, v, 1);
            v += __shfl_xor_sync(0xffffffffu, v, 2);
            if ((lane & 3) == 0)
                red[(w & 3) * 128 + wm + mi * 16 + h * 8 + (lane >> 2)] = v;
        }
    __syncthreads();

    // vectorized P store: 128 rows x 16 uint4 = 2048 uint4, 4/thread
    bf16* Pb = P + (size_t)b * T_ * T_;
    #pragma unroll
    for (int j = 0; j < 4; j++) {
        int u = tid + j * 512;
        int row = u >> 4, c = (u & 15) * 8;
        *reinterpret_cast<uint4*>(&Pb[(size_t)(t0 + row) * T_ + s0 + c]) =
            *reinterpret_cast<const uint4*>(&stg[row * 136 + c]);
    }
    if (tid < 128) {
        float tot = red[tid] + red[128 + tid] + red[256 + tid] + red[384 + tid];
        partial[((size_t)b * 16 + blockIdx.x) * T_ + t0 + tid] = tot;
    }
}

__global__ void inv_rs(const float* __restrict__ partial, float* __restrict__ inv) {
    int idx = blockIdx.x * 256 + threadIdx.x;
    int b = idx >> 11;
    int t = idx & (T_ - 1);
    const float* p = partial + (size_t)b * 16 * T_ + t;
    float s = 0.0f;
    #pragma unroll
    for (int j = 0; j < 16; j++) s += p[j * T_];
    inv[idx] = 1.0f / s;
}

// ---------------------------------------------------------------------------
// Output GEMM v3: 128x128 tile, 512 threads = 16 warps (4m x 4n),
// warp tile 32x32, cp.async double-buffered K-chunks of 64.
// ---------------------------------------------------------------------------
#define OA0 0u
#define OA1 18432u
#define OB0 36864u
#define OB1 55296u
#define OUT_SMEM 73728u

__device__ __forceinline__ void out_issue_chunk(const bf16* Vb, const bf16* Pb,
                                                int m0, int n0, int kc,
                                                uint32_t sb, int buf, int tid)
{
    const uint32_t aoff = buf ? OA1 : OA0;
    const uint32_t boff = buf ? OB1 : OB0;
    // 1024 uint4 per tile, 512 threads -> 2 per thread per tile
    #pragma unroll
    for (int j = 0; j < 2; j++) {
        int u = tid + j * 512;
        int row = u >> 3, c16 = u & 7;
        cp16(sb + aoff + (uint32_t)(row * 144 + c16 * 16),
             &Vb[(size_t)(m0 + row) * T_ + kc + c16 * 8]);
    }
    #pragma unroll
    for (int j = 0; j < 2; j++) {
        int u = tid + j * 512;
        int row = u >> 3, c16 = u & 7;
        cp16(sb + boff + (uint32_t)(row * 144 + c16 * 16),
             &Pb[(size_t)(n0 + row) * T_ + kc + c16 * 8]);
    }
    CP_COMMIT();
}

__global__ void __launch_bounds__(512, 2)
out_mma3(const bf16* __restrict__ V, const bf16* __restrict__ P,
         const float* __restrict__ inv, const float* __restrict__ x,
         const float* __restrict__ gamma, float* __restrict__ O)
{
    extern __shared__ __align__(128) char smem[];
    const uint32_t sb = cvta_s(smem);

    const int b  = blockIdx.z;
    const int n0 = blockIdx.x * 128;   // t
    const int m0 = blockIdx.y * 128;   // c
    const bf16* Vb = V + (size_t)b * C_ * T_;
    const bf16* Pb = P + (size_t)b * T_ * T_;

    const int tid  = threadIdx.x;
    const int lane = tid & 31;
    const int w    = tid >> 5;
    const int wm   = (w >> 2) * 32;
    const int wn   = (w & 3) * 32;

    float acc[2][4][4] = {};

    out_issue_chunk(Vb, Pb, m0, n0, 0,  sb, 0, tid);
    out_issue_chunk(Vb, Pb, m0, n0, 64, sb, 1, tid);

    #pragma unroll 1
    for (int ch = 0; ch < 32; ch++) {
        const int buf = ch & 1;
        if (ch < 31) { CP_WAIT(1); } else { CP_WAIT(0); }
        __syncthreads();

        const bf16* sA = reinterpret_cast<const bf16*>(smem + (buf ? OA1 : OA0));
        const bf16* sB = reinterpret_cast<const bf16*>(smem + (buf ? OB1 : OB0));

        #pragma unroll
        for (int kk = 0; kk < 64; kk += 16) {
            uint32_t af[2][4], bf_[4][2];
            #pragma unroll
            for (int mi = 0; mi < 2; mi++) {
                uint32_t a = cvta_s(&sA[(wm + mi * 16 + (lane & 15)) * 72 + kk + (lane >> 4) * 8]);
                ldsm_x4(af[mi], a);
            }
            #pragma unroll
            for (int p = 0; p < 2; p++) {
                uint32_t tmp[4];
                uint32_t a = cvta_s(&sB[(wn + p * 16 + (lane >> 4) * 8 + (lane & 7)) * 72 +
                                        kk + ((lane >> 3) & 1) * 8]);
                ldsm_x4(tmp, a);
                bf_[2 * p][0] = tmp[0]; bf_[2 * p][1] = tmp[1];
                bf_[2 * p + 1][0] = tmp[2]; bf_[2 * p + 1][1] = tmp[3];
            }
            #pragma unroll
            for (int mi = 0; mi < 2; mi++)
                #pragma unroll
                for (int ni = 0; ni < 4; ni++)
                    mma_bf16(acc[mi][ni], af[mi], bf_[ni]);
        }
        __syncthreads();

        if (ch + 2 < 32)
            out_issue_chunk(Vb, Pb, m0, n0, (ch + 2) * 64, sb, buf, tid);
    }

    const float g = gamma[0];
    const float* invB = inv + (size_t)b * T_;
    #pragma unroll
    for (int mi = 0; mi < 2; mi++) {
        int grow = m0 + wm + mi * 16 + (lane >> 2);
        #pragma unroll
        for (int ni = 0; ni < 4; ni++) {
            int gcol = n0 + wn + ni * 8 + (lane & 3) * 2;
            float2 iv = *reinterpret_cast<const float2*>(&invB[gcol]);
            size_t i0 = (size_t)b * C_ * T_ + (size_t)grow * T_ + gcol;
            size_t i1 = (size_t)b * C_ * T_ + (size_t)(grow + 8) * T_ + gcol;
            float2 x0 = *reinterpret_cast<const float2*>(&x[i0]);
            float2 x1 = *reinterpret_cast<const float2*>(&x[i1]);
            *reinterpret_cast<float2*>(&O[i0]) =
                make_float2(g * acc[mi][ni][0] * iv.x + x0.x, g * acc[mi][ni][1] * iv.y + x0.y);
            *reinterpret_cast<float2*>(&O[i1]) =
                make_float2(g * acc[mi][ni][2] * iv.x + x1.x, g * acc[mi][ni][3] * iv.y + x1.y);
        }
    }
}

// ---------------------------------------------------------------------------
// Launch
// ---------------------------------------------------------------------------
extern "C" void kernel_launch(void* const* d_in, const int* in_sizes, int n_in,
                              void* d_out, int out_size)
{
    const float* x     = (const float*)d_in[0];
    const float* wq    = (const float*)d_in[1];
    const float* bq    = (const float*)d_in[2];
    const float* wk    = (const float*)d_in[3];
    const float* bk    = (const float*)d_in[4];
    const float* wv    = (const float*)d_in[5];
    const float* bv    = (const float*)d_in[6];
    const float* gamma = (const float*)d_in[7];
    float* out = (float*)d_out;

    bf16 *xb, *wqb, *wkb, *wvb, *qb, *kb, *vb, *pb;
    float *rs, *inv;
    cudaGetSymbolAddress((void**)&xb,  g_xb);
    cudaGetSymbolAddress((void**)&wqb, g_wqb);
    cudaGetSymbolAddress((void**)&wkb, g_wkb);
    cudaGetSymbolAddress((void**)&wvb, g_wvb);
    cudaGetSymbolAddress((void**)&qb,  g_qb);
    cudaGetSymbolAddress((void**)&kb,  g_kb);
    cudaGetSymbolAddress((void**)&vb,  g_vb);
    cudaGetSymbolAddress((void**)&pb,  g_p);
    cudaGetSymbolAddress((void**)&rs,  g_rs);
    cudaGetSymbolAddress((void**)&inv, g_inv);

    cudaFuncSetAttribute(out_mma3, cudaFuncAttributeMaxDynamicSharedMemorySize, OUT_SMEM);

    // converts
    {
        int n4 = (B_ * C_ * T_) / 4;
        f2b_kernel<<<(n4 + 255) / 256, 256>>>(x, xb, n4);
        int nq4 = (CQ_ * C_) / 4, nv4 = (C_ * C_) / 4;
        int tot = nq4 + nq4 + nv4;
        f2b_w<<<(tot + 255) / 256, 256>>>(wq, wqb, nq4, wk, wkb, nq4, wv, wvb, nv4);
    }

    // all three projections in one launch
    proj_all<<<dim3(T_ / 128, 10, B_), 256>>>(wqb, bq, qb, wkb, bk, kb, wvb, bv, vb, xb);

    // scores + exp + partial row sums
    score_exp3<<<dim3(T_ / 128, T_ / 128, B_), 512>>>(qb, kb, pb, rs);

    // row-sum inverse
    inv_rs<<<(B_ * T_) / 256, 256>>>(rs, inv);

    // output GEMM
    out_mma3<<<dim3(T_ / 128, C_ / 128, B_), 512, OUT_SMEM>>>(vb, pb, inv, x, gamma, out);
}

// round 9
// speedup vs baseline: 1.0301x; 1.0301x over previous
#include <cuda_runtime.h>
#include <cuda_bf16.h>
#include <cstdint>

using bf16 = __nv_bfloat16;

#define B_  8
#define C_  512
#define T_  2048
#define CQ_ 64

// ---------------------------------------------------------------------------
// Device-global scratch
// ---------------------------------------------------------------------------
__device__ bf16  g_xb [B_ * C_ * T_];
__device__ bf16  g_wqb[CQ_ * C_];
__device__ bf16  g_wkb[CQ_ * C_];
__device__ bf16  g_wvb[C_ * C_];
__device__ bf16  g_qb [B_ * CQ_ * T_];
__device__ bf16  g_kb [B_ * CQ_ * T_];
__device__ bf16  g_vb [B_ * C_  * T_];
__device__ bf16  g_p  [(size_t)B_ * T_ * T_];
__device__ float g_rs [B_ * 16 * T_];
__device__ float g_inv[B_ * T_];

// ---------------------------------------------------------------------------
// PTX helpers
// ---------------------------------------------------------------------------
__device__ __forceinline__ uint32_t cvta_s(const void* p) {
    return (uint32_t)__cvta_generic_to_shared(p);
}
__device__ __forceinline__ void ldsm_x4(uint32_t* r, uint32_t a) {
    asm volatile("ldmatrix.sync.aligned.m8n8.x4.shared.b16 {%0,%1,%2,%3},[%4];"
                 : "=r"(r[0]), "=r"(r[1]), "=r"(r[2]), "=r"(r[3]) : "r"(a));
}
__device__ __forceinline__ void ldsm_x4t(uint32_t* r, uint32_t a) {
    asm volatile("ldmatrix.sync.aligned.m8n8.x4.trans.shared.b16 {%0,%1,%2,%3},[%4];"
                 : "=r"(r[0]), "=r"(r[1]), "=r"(r[2]), "=r"(r[3]) : "r"(a));
}
__device__ __forceinline__ void ldsm_x2t(uint32_t* r, uint32_t a) {
    asm volatile("ldmatrix.sync.aligned.m8n8.x2.trans.shared.b16 {%0,%1},[%2];"
                 : "=r"(r[0]), "=r"(r[1]) : "r"(a));
}
__device__ __forceinline__ void mma_bf16(float* c, const uint32_t* a, const uint32_t* b) {
    asm volatile("mma.sync.aligned.m16n8k16.row.col.f32.bf16.bf16.f32 "
                 "{%0,%1,%2,%3},{%4,%5,%6,%7},{%8,%9},{%0,%1,%2,%3};"
                 : "+f"(c[0]), "+f"(c[1]), "+f"(c[2]), "+f"(c[3])
                 : "r"(a[0]), "r"(a[1]), "r"(a[2]), "r"(a[3]), "r"(b[0]), "r"(b[1]));
}
__device__ __forceinline__ void cp16(uint32_t dst, const void* src) {
    asm volatile("cp.async.ca.shared.global [%0], [%1], 16;" :: "r"(dst), "l"(src));
}
#define CP_COMMIT() asm volatile("cp.async.commit_group;" ::: "memory")
#define CP_WAIT(n)  asm volatile("cp.async.wait_group %0;" :: "n"(n) : "memory")

// ---------------------------------------------------------------------------
// fp32 -> bf16 converts
// ---------------------------------------------------------------------------
__device__ __forceinline__ void cvt4(const float* in, bf16* out, int i) {
    float4 v = *reinterpret_cast<const float4*>(in + (size_t)i * 4);
    __nv_bfloat162 lo = __floats2bfloat162_rn(v.x, v.y);
    __nv_bfloat162 hi = __floats2bfloat162_rn(v.z, v.w);
    uint2 pk;
    pk.x = *reinterpret_cast<uint32_t*>(&lo);
    pk.y = *reinterpret_cast<uint32_t*>(&hi);
    *reinterpret_cast<uint2*>(out + (size_t)i * 4) = pk;
}
__global__ void f2b_kernel(const float* __restrict__ in, bf16* __restrict__ out, int n4) {
    int i = blockIdx.x * blockDim.x + threadIdx.x;
    if (i < n4) cvt4(in, out, i);
}
__global__ void f2b_w(const float* __restrict__ a, bf16* __restrict__ ao, int na4,
                      const float* __restrict__ b, bf16* __restrict__ bo, int nb4,
                      const float* __restrict__ c, bf16* __restrict__ co, int nc4) {
    int i = blockIdx.x * blockDim.x + threadIdx.x;
    if (i < na4)                    cvt4(a, ao, i);
    else if (i < na4 + nb4)         cvt4(b, bo, i - na4);
    else if (i < na4 + nb4 + nc4)   cvt4(c, co, i - na4 - nb4);
}

// ---------------------------------------------------------------------------
// Fused projections (validated): blockIdx.y: 0=q, 1=k, 2..9=v tiles.
// ---------------------------------------------------------------------------
__global__ void proj_all(const bf16* __restrict__ wq, const float* __restrict__ bq, bf16* __restrict__ q,
                         const bf16* __restrict__ wk, const float* __restrict__ bk, bf16* __restrict__ k,
                         const bf16* __restrict__ wv, const float* __restrict__ bv, bf16* __restrict__ v,
                         const bf16* __restrict__ X)
{
    __shared__ bf16 sA[64][72];
    __shared__ bf16 sB[64][136];

    const int y = blockIdx.y;
    const bf16* W; const float* bias; bf16* Out; int m0; int Mrows;
    if (y == 0)      { W = wq; bias = bq; Out = q; m0 = 0;            Mrows = CQ_; }
    else if (y == 1) { W = wk; bias = bk; Out = k; m0 = 0;            Mrows = CQ_; }
    else             { W = wv; bias = bv; Out = v; m0 = (y - 2) * 64; Mrows = C_;  }

    const int b  = blockIdx.z;
    const int n0 = blockIdx.x * 128;
    const bf16* Xb = X + (size_t)b * C_ * T_;
    bf16*       Ob = Out + (size_t)b * Mrows * T_;

    const int tid  = threadIdx.x;
    const int lane = tid & 31;
    const int w    = tid >> 5;
    const int wm   = (w >> 2) * 32;
    const int wn   = (w & 3) * 32;

    float acc[2][4][4] = {};

    for (int kc = 0; kc < C_; kc += 64) {
        {
            int r = tid >> 3, c = (tid & 7) * 8;
            #pragma unroll
            for (int p = 0; p < 2; p++)
                *reinterpret_cast<uint4*>(&sA[r + p * 32][c]) =
                    *reinterpret_cast<const uint4*>(&W[(size_t)(m0 + r + p * 32) * C_ + kc + c]);
        }
        {
            int r = tid >> 4, c = (tid & 15) * 8;
            #pragma unroll
            for (int p = 0; p < 4; p++)
                *reinterpret_cast<uint4*>(&sB[r + p * 16][c]) =
                    *reinterpret_cast<const uint4*>(&Xb[(size_t)(kc + r + p * 16) * T_ + n0 + c]);
        }
        __syncthreads();

        #pragma unroll
        for (int kk = 0; kk < 64; kk += 16) {
            uint32_t af[2][4], bf_[4][2];
            #pragma unroll
            for (int mi = 0; mi < 2; mi++) {
                uint32_t a = cvta_s(&sA[wm + mi * 16 + (lane & 15)][kk + (lane >> 4) * 8]);
                ldsm_x4(af[mi], a);
            }
            #pragma unroll
            for (int ni = 0; ni < 4; ni++) {
                int r = kk + ((lane >> 3) & 1) * 8 + (lane & 7);
                uint32_t a = cvta_s(&sB[r][wn + ni * 8]);
                ldsm_x2t(bf_[ni], a);
            }
            #pragma unroll
            for (int mi = 0; mi < 2; mi++)
                #pragma unroll
                for (int ni = 0; ni < 4; ni++)
                    mma_bf16(acc[mi][ni], af[mi], bf_[ni]);
        }
        __syncthreads();
    }

    #pragma unroll
    for (int mi = 0; mi < 2; mi++) {
        int grow = m0 + wm + mi * 16 + (lane >> 2);
        float bv0 = bias[grow];
        float bv1 = bias[grow + 8];
        #pragma unroll
        for (int ni = 0; ni < 4; ni++) {
            int gcol = n0 + wn + ni * 8 + (lane & 3) * 2;
            __nv_bfloat162 v0 = __floats2bfloat162_rn(acc[mi][ni][0] + bv0, acc[mi][ni][1] + bv0);
            __nv_bfloat162 v1 = __floats2bfloat162_rn(acc[mi][ni][2] + bv1, acc[mi][ni][3] + bv1);
            *reinterpret_cast<__nv_bfloat162*>(&Ob[(size_t)grow * T_ + gcol]) = v0;
            *reinterpret_cast<__nv_bfloat162*>(&Ob[(size_t)(grow + 8) * T_ + gcol]) = v1;
        }
    }
}

// ---------------------------------------------------------------------------
// Scores + exp (round-7 version, 256 threads, warp tile 64x32 — validated best)
// ---------------------------------------------------------------------------
__global__ void __launch_bounds__(256)
score_exp2(const bf16* __restrict__ Q, const bf16* __restrict__ Km,
           bf16* __restrict__ P, float* __restrict__ partial)
{
    __shared__ __align__(16) char sm[34816 + 2048];
    bf16*  sQ  = reinterpret_cast<bf16*>(sm);            // [64][136] (o, t)
    bf16*  sK  = reinterpret_cast<bf16*>(sm + 17408);    // [64][136] (o, s)
    bf16*  stg = reinterpret_cast<bf16*>(sm);            // [128][136] overlays Q/K
    float* red = reinterpret_cast<float*>(sm + 34816);   // [4][128]

    const int b  = blockIdx.z;
    const int s0 = blockIdx.x * 128;
    const int t0 = blockIdx.y * 128;
    const bf16* Qb = Q  + (size_t)b * CQ_ * T_;
    const bf16* Kb = Km + (size_t)b * CQ_ * T_;

    const int tid  = threadIdx.x;
    const int lane = tid & 31;
    const int w    = tid >> 5;
    const int wm   = (w >> 2) * 64;   // t warp offset (0 or 64)
    const int wn   = (w & 3) * 32;    // s warp offset

    #pragma unroll
    for (int i = 0; i < 4; i++) {
        int u = tid + i * 256;
        int r = u >> 4, c = (u & 15) * 8;
        *reinterpret_cast<uint4*>(&sQ[r * 136 + c]) =
            *reinterpret_cast<const uint4*>(&Qb[(size_t)r * T_ + t0 + c]);
        *reinterpret_cast<uint4*>(&sK[r * 136 + c]) =
            *reinterpret_cast<const uint4*>(&Kb[(size_t)r * T_ + s0 + c]);
    }
    __syncthreads();

    float acc[4][4][4] = {};

    #pragma unroll
    for (int kk = 0; kk < 64; kk += 16) {
        uint32_t af[4][4], bf_[4][2];
        const int g = lane >> 3;
        #pragma unroll
        for (int mi = 0; mi < 4; mi++) {
            uint32_t a = cvta_s(&sQ[(kk + (g >> 1) * 8 + (lane & 7)) * 136 +
                                    wm + mi * 16 + (g & 1) * 8]);
            ldsm_x4t(af[mi], a);
        }
        #pragma unroll
        for (int p = 0; p < 2; p++) {
            uint32_t tmp[4];
            uint32_t a = cvta_s(&sK[(kk + ((lane >> 3) & 1) * 8 + (lane & 7)) * 136 +
                                    wn + p * 16 + (lane >> 4) * 8]);
            ldsm_x4t(tmp, a);
            bf_[2 * p][0] = tmp[0]; bf_[2 * p][1] = tmp[1];
            bf_[2 * p + 1][0] = tmp[2]; bf_[2 * p + 1][1] = tmp[3];
        }
        #pragma unroll
        for (int mi = 0; mi < 4; mi++)
            #pragma unroll
            for (int ni = 0; ni < 4; ni++)
                mma_bf16(acc[mi][ni], af[mi], bf_[ni]);
    }
    __syncthreads();

    float rs[4][2] = {};
    #pragma unroll
    for (int mi = 0; mi < 4; mi++) {
        int r0 = wm + mi * 16 + (lane >> 2);
        #pragma unroll
        for (int ni = 0; ni < 4; ni++) {
            float p0 = __expf(acc[mi][ni][0]);
            float p1 = __expf(acc[mi][ni][1]);
            float p2 = __expf(acc[mi][ni][2]);
            float p3 = __expf(acc[mi][ni][3]);
            rs[mi][0] += p0 + p1;
            rs[mi][1] += p2 + p3;
            int cc = wn + ni * 8 + (lane & 3) * 2;
            __nv_bfloat162 lo = __floats2bfloat162_rn(p0, p1);
            __nv_bfloat162 hi = __floats2bfloat162_rn(p2, p3);
            *reinterpret_cast<__nv_bfloat162*>(&stg[r0 * 136 + cc]) = lo;
            *reinterpret_cast<__nv_bfloat162*>(&stg[(r0 + 8) * 136 + cc]) = hi;
        }
    }
    #pragma unroll
    for (int mi = 0; mi < 4; mi++)
        #pragma unroll
        for (int h = 0; h < 2; h++) {
            float v = rs[mi][h];
            v += __shfl_xor_sync(0xffffffffu, v, 1);
            v += __shfl_xor_sync(0xffffffffu, v, 2);
            if ((lane & 3) == 0)
                red[(w & 3) * 128 + wm + mi * 16 + h * 8 + (lane >> 2)] = v;
        }
    __syncthreads();

    bf16* Pb = P + (size_t)b * T_ * T_;
    #pragma unroll
    for (int j = 0; j < 8; j++) {
        int u = tid + j * 256;
        int row = u >> 4, c = (u & 15) * 8;
        *reinterpret_cast<uint4*>(&Pb[(size_t)(t0 + row) * T_ + s0 + c]) =
            *reinterpret_cast<const uint4*>(&stg[row * 136 + c]);
    }
    if (tid < 128) {
        float tot = red[tid] + red[128 + tid] + red[256 + tid] + red[384 + tid];
        partial[((size_t)b * 16 + blockIdx.x) * T_ + t0 + tid] = tot;
    }
}

__global__ void inv_rs(const float* __restrict__ partial, float* __restrict__ inv) {
    int idx = blockIdx.x * 256 + threadIdx.x;
    int b = idx >> 11;
    int t = idx & (T_ - 1);
    const float* p = partial + (size_t)b * 16 * T_ + t;
    float s = 0.0f;
    #pragma unroll
    for (int j = 0; j < 16; j++) s += p[j * T_];
    inv[idx] = 1.0f / s;
}

// ---------------------------------------------------------------------------
// Output GEMM v4: 256(c) x 128(t) tiles — halves P re-reads (L2 traffic
// 540 -> 400 MB). 512 threads = 16 warps (4m x 4n), warp tile 64x32,
// cp.async double-buffered K-chunks of 64.
// smem: A[2][256][72] + B[2][128][72] bf16 = 110592 B.
// ---------------------------------------------------------------------------
#define O4_A0 0u
#define O4_A1 36864u
#define O4_B0 73728u
#define O4_B1 92160u
#define OUT_SMEM 110592u

__device__ __forceinline__ void out_issue_chunk4(const bf16* Vb, const bf16* Pb,
                                                 int m0, int n0, int kc,
                                                 uint32_t sb, int buf, int tid)
{
    const uint32_t aoff = buf ? O4_A1 : O4_A0;
    const uint32_t boff = buf ? O4_B1 : O4_B0;
    // A: 256 rows x 64 cols = 2048 uint4, 512 threads -> 4/thread
    #pragma unroll
    for (int j = 0; j < 4; j++) {
        int u = tid + j * 512;
        int row = u >> 3, c16 = u & 7;
        cp16(sb + aoff + (uint32_t)(row * 144 + c16 * 16),
             &Vb[(size_t)(m0 + row) * T_ + kc + c16 * 8]);
    }
    // B: 128 rows x 64 cols = 1024 uint4 -> 2/thread
    #pragma unroll
    for (int j = 0; j < 2; j++) {
        int u = tid + j * 512;
        int row = u >> 3, c16 = u & 7;
        cp16(sb + boff + (uint32_t)(row * 144 + c16 * 16),
             &Pb[(size_t)(n0 + row) * T_ + kc + c16 * 8]);
    }
    CP_COMMIT();
}

__global__ void __launch_bounds__(512, 1)
out_mma4(const bf16* __restrict__ V, const bf16* __restrict__ P,
         const float* __restrict__ inv, const float* __restrict__ x,
         const float* __restrict__ gamma, float* __restrict__ O)
{
    extern __shared__ __align__(128) char smem[];
    const uint32_t sb = cvta_s(smem);

    const int b  = blockIdx.z;
    const int n0 = blockIdx.x * 128;   // t
    const int m0 = blockIdx.y * 256;   // c
    const bf16* Vb = V + (size_t)b * C_ * T_;
    const bf16* Pb = P + (size_t)b * T_ * T_;

    const int tid  = threadIdx.x;
    const int lane = tid & 31;
    const int w    = tid >> 5;
    const int wm   = (w >> 2) * 64;    // c warp offset: 0,64,128,192
    const int wn   = (w & 3) * 32;     // t warp offset

    float acc[4][4][4] = {};

    out_issue_chunk4(Vb, Pb, m0, n0, 0,  sb, 0, tid);
    out_issue_chunk4(Vb, Pb, m0, n0, 64, sb, 1, tid);

    #pragma unroll 1
    for (int ch = 0; ch < 32; ch++) {
        const int buf = ch & 1;
        if (ch < 31) { CP_WAIT(1); } else { CP_WAIT(0); }
        __syncthreads();

        const bf16* sA = reinterpret_cast<const bf16*>(smem + (buf ? O4_A1 : O4_A0));
        const bf16* sB = reinterpret_cast<const bf16*>(smem + (buf ? O4_B1 : O4_B0));

        #pragma unroll
        for (int kk = 0; kk < 64; kk += 16) {
            uint32_t af[4][4], bf_[4][2];
            #pragma unroll
            for (int mi = 0; mi < 4; mi++) {
                uint32_t a = cvta_s(&sA[(wm + mi * 16 + (lane & 15)) * 72 + kk + (lane >> 4) * 8]);
                ldsm_x4(af[mi], a);
            }
            #pragma unroll
            for (int p = 0; p < 2; p++) {
                uint32_t tmp[4];
                uint32_t a = cvta_s(&sB[(wn + p * 16 + (lane >> 4) * 8 + (lane & 7)) * 72 +
                                        kk + ((lane >> 3) & 1) * 8]);
                ldsm_x4(tmp, a);
                bf_[2 * p][0] = tmp[0]; bf_[2 * p][1] = tmp[1];
                bf_[2 * p + 1][0] = tmp[2]; bf_[2 * p + 1][1] = tmp[3];
            }
            #pragma unroll
            for (int mi = 0; mi < 4; mi++)
                #pragma unroll
                for (int ni = 0; ni < 4; ni++)
                    mma_bf16(acc[mi][ni], af[mi], bf_[ni]);
        }
        __syncthreads();

        if (ch + 2 < 32)
            out_issue_chunk4(Vb, Pb, m0, n0, (ch + 2) * 64, sb, buf, tid);
    }

    const float g = gamma[0];
    const float* invB = inv + (size_t)b * T_;
    #pragma unroll
    for (int mi = 0; mi < 4; mi++) {
        int grow = m0 + wm + mi * 16 + (lane >> 2);
        #pragma unroll
        for (int ni = 0; ni < 4; ni++) {
            int gcol = n0 + wn + ni * 8 + (lane & 3) * 2;
            float2 iv = *reinterpret_cast<const float2*>(&invB[gcol]);
            size_t i0 = (size_t)b * C_ * T_ + (size_t)grow * T_ + gcol;
            size_t i1 = (size_t)b * C_ * T_ + (size_t)(grow + 8) * T_ + gcol;
            float2 x0 = *reinterpret_cast<const float2*>(&x[i0]);
            float2 x1 = *reinterpret_cast<const float2*>(&x[i1]);
            *reinterpret_cast<float2*>(&O[i0]) =
                make_float2(g * acc[mi][ni][0] * iv.x + x0.x, g * acc[mi][ni][1] * iv.y + x0.y);
            *reinterpret_cast<float2*>(&O[i1]) =
                make_float2(g * acc[mi][ni][2] * iv.x + x1.x, g * acc[mi][ni][3] * iv.y + x1.y);
        }
    }
}

// ---------------------------------------------------------------------------
// Launch
// ---------------------------------------------------------------------------
extern "C" void kernel_launch(void* const* d_in, const int* in_sizes, int n_in,
                              void* d_out, int out_size)
{
    const float* x     = (const float*)d_in[0];
    const float* wq    = (const float*)d_in[1];
    const float* bq    = (const float*)d_in[2];
    const float* wk    = (const float*)d_in[3];
    const float* bk    = (const float*)d_in[4];
    const float* wv    = (const float*)d_in[5];
    const float* bv    = (const float*)d_in[6];
    const float* gamma = (const float*)d_in[7];
    float* out = (float*)d_out;

    bf16 *xb, *wqb, *wkb, *wvb, *qb, *kb, *vb, *pb;
    float *rs, *inv;
    cudaGetSymbolAddress((void**)&xb,  g_xb);
    cudaGetSymbolAddress((void**)&wqb, g_wqb);
    cudaGetSymbolAddress((void**)&wkb, g_wkb);
    cudaGetSymbolAddress((void**)&wvb, g_wvb);
    cudaGetSymbolAddress((void**)&qb,  g_qb);
    cudaGetSymbolAddress((void**)&kb,  g_kb);
    cudaGetSymbolAddress((void**)&vb,  g_vb);
    cudaGetSymbolAddress((void**)&pb,  g_p);
    cudaGetSymbolAddress((void**)&rs,  g_rs);
    cudaGetSymbolAddress((void**)&inv, g_inv);

    cudaFuncSetAttribute(out_mma4, cudaFuncAttributeMaxDynamicSharedMemorySize, OUT_SMEM);

    // converts
    {
        int n4 = (B_ * C_ * T_) / 4;
        f2b_kernel<<<(n4 + 255) / 256, 256>>>(x, xb, n4);
        int nq4 = (CQ_ * C_) / 4, nv4 = (C_ * C_) / 4;
        int tot = nq4 + nq4 + nv4;
        f2b_w<<<(tot + 255) / 256, 256>>>(wq, wqb, nq4, wk, wkb, nq4, wv, wvb, nv4);
    }

    // all three projections in one launch
    proj_all<<<dim3(T_ / 128, 10, B_), 256>>>(wqb, bq, qb, wkb, bk, kb, wvb, bv, vb, xb);

    // scores + exp + partial row sums
    score_exp2<<<dim3(T_ / 128, T_ / 128, B_), 256>>>(qb, kb, pb, rs);

    // row-sum inverse
    inv_rs<<<(B_ * T_) / 256, 256>>>(rs, inv);

    // output GEMM: 256x128 tiles
    out_mma4<<<dim3(T_ / 128, C_ / 256, B_), 512, OUT_SMEM>>>(vb, pb, inv, x, gamma, out);
}

// round 10
// speedup vs baseline: 1.0819x; 1.0503x over previous
#include <cuda_runtime.h>
#include <cuda_bf16.h>
#include <cstdint>

using bf16 = __nv_bfloat16;

#define B_  8
#define C_  512
#define T_  2048
#define CQ_ 64

// ---------------------------------------------------------------------------
// Device-global scratch
// ---------------------------------------------------------------------------
__device__ bf16  g_xb [B_ * C_ * T_];
__device__ bf16  g_wqb[CQ_ * C_];
__device__ bf16  g_wkb[CQ_ * C_];
__device__ bf16  g_wvb[C_ * C_];
__device__ bf16  g_qb [B_ * CQ_ * T_];
__device__ bf16  g_kb [B_ * CQ_ * T_];
__device__ bf16  g_vb [B_ * C_  * T_];
__device__ bf16  g_p  [(size_t)B_ * T_ * T_];
__device__ float g_rs [B_ * 8 * T_];      // partial row sums [b][sblk(8)][t]

// ---------------------------------------------------------------------------
// PTX helpers
// ---------------------------------------------------------------------------
__device__ __forceinline__ uint32_t cvta_s(const void* p) {
    return (uint32_t)__cvta_generic_to_shared(p);
}
__device__ __forceinline__ void ldsm_x4(uint32_t* r, uint32_t a) {
    asm volatile("ldmatrix.sync.aligned.m8n8.x4.shared.b16 {%0,%1,%2,%3},[%4];"
                 : "=r"(r[0]), "=r"(r[1]), "=r"(r[2]), "=r"(r[3]) : "r"(a));
}
__device__ __forceinline__ void ldsm_x4t(uint32_t* r, uint32_t a) {
    asm volatile("ldmatrix.sync.aligned.m8n8.x4.trans.shared.b16 {%0,%1,%2,%3},[%4];"
                 : "=r"(r[0]), "=r"(r[1]), "=r"(r[2]), "=r"(r[3]) : "r"(a));
}
__device__ __forceinline__ void ldsm_x2t(uint32_t* r, uint32_t a) {
    asm volatile("ldmatrix.sync.aligned.m8n8.x2.trans.shared.b16 {%0,%1},[%2];"
                 : "=r"(r[0]), "=r"(r[1]) : "r"(a));
}
__device__ __forceinline__ void mma_bf16(float* c, const uint32_t* a, const uint32_t* b) {
    asm volatile("mma.sync.aligned.m16n8k16.row.col.f32.bf16.bf16.f32 "
                 "{%0,%1,%2,%3},{%4,%5,%6,%7},{%8,%9},{%0,%1,%2,%3};"
                 : "+f"(c[0]), "+f"(c[1]), "+f"(c[2]), "+f"(c[3])
                 : "r"(a[0]), "r"(a[1]), "r"(a[2]), "r"(a[3]), "r"(b[0]), "r"(b[1]));
}
__device__ __forceinline__ void cp16(uint32_t dst, const void* src) {
    asm volatile("cp.async.ca.shared.global [%0], [%1], 16;" :: "r"(dst), "l"(src));
}
#define CP_COMMIT() asm volatile("cp.async.commit_group;" ::: "memory")
#define CP_WAIT(n)  asm volatile("cp.async.wait_group %0;" :: "n"(n) : "memory")

// ---------------------------------------------------------------------------
// fp32 -> bf16 converts
// ---------------------------------------------------------------------------
__device__ __forceinline__ void cvt4(const float* in, bf16* out, int i) {
    float4 v = *reinterpret_cast<const float4*>(in + (size_t)i * 4);
    __nv_bfloat162 lo = __floats2bfloat162_rn(v.x, v.y);
    __nv_bfloat162 hi = __floats2bfloat162_rn(v.z, v.w);
    uint2 pk;
    pk.x = *reinterpret_cast<uint32_t*>(&lo);
    pk.y = *reinterpret_cast<uint32_t*>(&hi);
    *reinterpret_cast<uint2*>(out + (size_t)i * 4) = pk;
}
__global__ void f2b_kernel(const float* __restrict__ in, bf16* __restrict__ out, int n4) {
    int i = blockIdx.x * blockDim.x + threadIdx.x;
    if (i < n4) cvt4(in, out, i);
}
__global__ void f2b_w(const float* __restrict__ a, bf16* __restrict__ ao, int na4,
                      const float* __restrict__ b, bf16* __restrict__ bo, int nb4,
                      const float* __restrict__ c, bf16* __restrict__ co, int nc4) {
    int i = blockIdx.x * blockDim.x + threadIdx.x;
    if (i < na4)                    cvt4(a, ao, i);
    else if (i < na4 + nb4)         cvt4(b, bo, i - na4);
    else if (i < na4 + nb4 + nc4)   cvt4(c, co, i - na4 - nb4);
}

// ---------------------------------------------------------------------------
// Fused projections (validated): blockIdx.y: 0=q, 1=k, 2..9=v tiles.
// ---------------------------------------------------------------------------
__global__ void proj_all(const bf16* __restrict__ wq, const float* __restrict__ bq, bf16* __restrict__ q,
                         const bf16* __restrict__ wk, const float* __restrict__ bk, bf16* __restrict__ k,
                         const bf16* __restrict__ wv, const float* __restrict__ bv, bf16* __restrict__ v,
                         const bf16* __restrict__ X)
{
    __shared__ bf16 sA[64][72];
    __shared__ bf16 sB[64][136];

    const int y = blockIdx.y;
    const bf16* W; const float* bias; bf16* Out; int m0; int Mrows;
    if (y == 0)      { W = wq; bias = bq; Out = q; m0 = 0;            Mrows = CQ_; }
    else if (y == 1) { W = wk; bias = bk; Out = k; m0 = 0;            Mrows = CQ_; }
    else             { W = wv; bias = bv; Out = v; m0 = (y - 2) * 64; Mrows = C_;  }

    const int b  = blockIdx.z;
    const int n0 = blockIdx.x * 128;
    const bf16* Xb = X + (size_t)b * C_ * T_;
    bf16*       Ob = Out + (size_t)b * Mrows * T_;

    const int tid  = threadIdx.x;
    const int lane = tid & 31;
    const int w    = tid >> 5;
    const int wm   = (w >> 2) * 32;
    const int wn   = (w & 3) * 32;

    float acc[2][4][4] = {};

    for (int kc = 0; kc < C_; kc += 64) {
        {
            int r = tid >> 3, c = (tid & 7) * 8;
            #pragma unroll
            for (int p = 0; p < 2; p++)
                *reinterpret_cast<uint4*>(&sA[r + p * 32][c]) =
                    *reinterpret_cast<const uint4*>(&W[(size_t)(m0 + r + p * 32) * C_ + kc + c]);
        }
        {
            int r = tid >> 4, c = (tid & 15) * 8;
            #pragma unroll
            for (int p = 0; p < 4; p++)
                *reinterpret_cast<uint4*>(&sB[r + p * 16][c]) =
                    *reinterpret_cast<const uint4*>(&Xb[(size_t)(kc + r + p * 16) * T_ + n0 + c]);
        }
        __syncthreads();

        #pragma unroll
        for (int kk = 0; kk < 64; kk += 16) {
            uint32_t af[2][4], bf_[4][2];
            #pragma unroll
            for (int mi = 0; mi < 2; mi++) {
                uint32_t a = cvta_s(&sA[wm + mi * 16 + (lane & 15)][kk + (lane >> 4) * 8]);
                ldsm_x4(af[mi], a);
            }
            #pragma unroll
            for (int ni = 0; ni < 4; ni++) {
                int r = kk + ((lane >> 3) & 1) * 8 + (lane & 7);
                uint32_t a = cvta_s(&sB[r][wn + ni * 8]);
                ldsm_x2t(bf_[ni], a);
            }
            #pragma unroll
            for (int mi = 0; mi < 2; mi++)
                #pragma unroll
                for (int ni = 0; ni < 4; ni++)
                    mma_bf16(acc[mi][ni], af[mi], bf_[ni]);
        }
        __syncthreads();
    }

    #pragma unroll
    for (int mi = 0; mi < 2; mi++) {
        int grow = m0 + wm + mi * 16 + (lane >> 2);
        float bv0 = bias[grow];
        float bv1 = bias[grow + 8];
        #pragma unroll
        for (int ni = 0; ni < 4; ni++) {
            int gcol = n0 + wn + ni * 8 + (lane & 3) * 2;
            __nv_bfloat162 v0 = __floats2bfloat162_rn(acc[mi][ni][0] + bv0, acc[mi][ni][1] + bv0);
            __nv_bfloat162 v1 = __floats2bfloat162_rn(acc[mi][ni][2] + bv1, acc[mi][ni][3] + bv1);
            *reinterpret_cast<__nv_bfloat162*>(&Ob[(size_t)grow * T_ + gcol]) = v0;
            *reinterpret_cast<__nv_bfloat162*>(&Ob[(size_t)(grow + 8) * T_ + gcol]) = v1;
        }
    }
}

// ---------------------------------------------------------------------------
// Scores + exp v4: block = 128(t) x 256(s) — two s-tiles, Q loaded once,
// K chunk 1 prefetched via cp.async while chunk 0 computes.
// 256 threads = 8 warps (2m x 4n), warp tile 64x32 per s-tile.
// Dynamic smem: sQ 17408 | sK0 17408 | sK1 17408 | stg 34816 | red 2048
// ---------------------------------------------------------------------------
#define SC_Q    0u
#define SC_K0   17408u
#define SC_K1   34816u
#define SC_STG  52224u
#define SC_RED  87040u
#define SC_SMEM 89088u

__global__ void __launch_bounds__(256, 2)
score_exp4(const bf16* __restrict__ Q, const bf16* __restrict__ Km,
           bf16* __restrict__ P, float* __restrict__ partial)
{
    extern __shared__ __align__(16) char sm[];
    const uint32_t sb = cvta_s(sm);
    bf16*  sQ  = reinterpret_cast<bf16*>(sm + SC_Q);
    bf16*  stg = reinterpret_cast<bf16*>(sm + SC_STG);
    float* red = reinterpret_cast<float*>(sm + SC_RED);

    const int b   = blockIdx.z;
    const int s0g = blockIdx.x * 256;
    const int t0  = blockIdx.y * 128;
    const bf16* Qb = Q  + (size_t)b * CQ_ * T_;
    const bf16* Kb = Km + (size_t)b * CQ_ * T_;

    const int tid  = threadIdx.x;
    const int lane = tid & 31;
    const int w    = tid >> 5;
    const int wm   = (w >> 2) * 64;   // t warp offset (0 or 64)
    const int wn   = (w & 3) * 32;    // s warp offset

    // cp.async Q + K chunk0 (group 0), then K chunk1 (group 1)
    #pragma unroll
    for (int j = 0; j < 4; j++) {
        int u = tid + j * 256;
        int r = u >> 4, c16 = u & 15;
        cp16(sb + SC_Q + (uint32_t)(r * 272 + c16 * 16),
             &Qb[(size_t)r * T_ + t0 + c16 * 8]);
        cp16(sb + SC_K0 + (uint32_t)(r * 272 + c16 * 16),
             &Kb[(size_t)r * T_ + s0g + c16 * 8]);
    }
    CP_COMMIT();
    #pragma unroll
    for (int j = 0; j < 4; j++) {
        int u = tid + j * 256;
        int r = u >> 4, c16 = u & 15;
        cp16(sb + SC_K1 + (uint32_t)(r * 272 + c16 * 16),
             &Kb[(size_t)r * T_ + s0g + 128 + c16 * 8]);
    }
    CP_COMMIT();

    float rs[4][2] = {};
    bf16* Pb = P + (size_t)b * T_ * T_;

    #pragma unroll 1
    for (int it = 0; it < 2; it++) {
        if (it == 0) { CP_WAIT(1); } else { CP_WAIT(0); }
        __syncthreads();   // K[it] visible; stg free (WAR from prior store)

        const bf16* sK = reinterpret_cast<const bf16*>(sm + (it ? SC_K1 : SC_K0));

        float acc[4][4][4] = {};
        #pragma unroll
        for (int kk = 0; kk < 64; kk += 16) {
            uint32_t af[4][4], bf_[4][2];
            const int g = lane >> 3;
            #pragma unroll
            for (int mi = 0; mi < 4; mi++) {
                uint32_t a = cvta_s(&sQ[(kk + (g >> 1) * 8 + (lane & 7)) * 136 +
                                        wm + mi * 16 + (g & 1) * 8]);
                ldsm_x4t(af[mi], a);
            }
            #pragma unroll
            for (int p = 0; p < 2; p++) {
                uint32_t tmp[4];
                uint32_t a = cvta_s(&sK[(kk + ((lane >> 3) & 1) * 8 + (lane & 7)) * 136 +
                                        wn + p * 16 + (lane >> 4) * 8]);
                ldsm_x4t(tmp, a);
                bf_[2 * p][0] = tmp[0]; bf_[2 * p][1] = tmp[1];
                bf_[2 * p + 1][0] = tmp[2]; bf_[2 * p + 1][1] = tmp[3];
            }
            #pragma unroll
            for (int mi = 0; mi < 4; mi++)
                #pragma unroll
                for (int ni = 0; ni < 4; ni++)
                    mma_bf16(acc[mi][ni], af[mi], bf_[ni]);
        }

        // exp -> stg + row-sum partials
        #pragma unroll
        for (int mi = 0; mi < 4; mi++) {
            int r0 = wm + mi * 16 + (lane >> 2);
            #pragma unroll
            for (int ni = 0; ni < 4; ni++) {
                float p0 = __expf(acc[mi][ni][0]);
                float p1 = __expf(acc[mi][ni][1]);
                float p2 = __expf(acc[mi][ni][2]);
                float p3 = __expf(acc[mi][ni][3]);
                rs[mi][0] += p0 + p1;
                rs[mi][1] += p2 + p3;
                int cc = wn + ni * 8 + (lane & 3) * 2;
                __nv_bfloat162 lo = __floats2bfloat162_rn(p0, p1);
                __nv_bfloat162 hi = __floats2bfloat162_rn(p2, p3);
                *reinterpret_cast<__nv_bfloat162*>(&stg[r0 * 136 + cc]) = lo;
                *reinterpret_cast<__nv_bfloat162*>(&stg[(r0 + 8) * 136 + cc]) = hi;
            }
        }
        __syncthreads();   // stg writes visible

        // vectorized P store for this s-tile
        const int sg = s0g + it * 128;
        #pragma unroll
        for (int j = 0; j < 8; j++) {
            int u = tid + j * 256;
            int row = u >> 4, c = (u & 15) * 8;
            *reinterpret_cast<uint4*>(&Pb[(size_t)(t0 + row) * T_ + sg + c]) =
                *reinterpret_cast<const uint4*>(&stg[row * 136 + c]);
        }
    }

    // reduce rs (summed over both s-tiles) across lane&3 and the 4 n-warps
    #pragma unroll
    for (int mi = 0; mi < 4; mi++)
        #pragma unroll
        for (int h = 0; h < 2; h++) {
            float v = rs[mi][h];
            v += __shfl_xor_sync(0xffffffffu, v, 1);
            v += __shfl_xor_sync(0xffffffffu, v, 2);
            if ((lane & 3) == 0)
                red[(w & 3) * 128 + wm + mi * 16 + h * 8 + (lane >> 2)] = v;
        }
    __syncthreads();
    if (tid < 128) {
        float tot = red[tid] + red[128 + tid] + red[256 + tid] + red[384 + tid];
        partial[((size_t)b * 8 + blockIdx.x) * T_ + t0 + tid] = tot;
    }
}

// ---------------------------------------------------------------------------
// Output GEMM (round-7 winner) + fused inv computation in prologue.
// 128(c) x 128(t) tiles, 256 threads = 8 warps (2m x 4n), warp tile 64x32,
// cp.async double-buffered K-chunks of 64, paired-x4 B loads.
// ---------------------------------------------------------------------------
#define OA0 0u
#define OA1 18432u
#define OB0 36864u
#define OB1 55296u
#define OINV 73728u
#define OUT_SMEM 74240u

__device__ __forceinline__ void out_issue_chunk(const bf16* Vb, const bf16* Pb,
                                                int m0, int n0, int kc,
                                                uint32_t sb, int buf, int tid)
{
    const uint32_t aoff = buf ? OA1 : OA0;
    const uint32_t boff = buf ? OB1 : OB0;
    #pragma unroll
    for (int j = 0; j < 4; j++) {
        int u = tid + j * 256;
        int row = u >> 3, c16 = u & 7;
        cp16(sb + aoff + (uint32_t)(row * 144 + c16 * 16),
             &Vb[(size_t)(m0 + row) * T_ + kc + c16 * 8]);
    }
    #pragma unroll
    for (int j = 0; j < 4; j++) {
        int u = tid + j * 256;
        int row = u >> 3, c16 = u & 7;
        cp16(sb + boff + (uint32_t)(row * 144 + c16 * 16),
             &Pb[(size_t)(n0 + row) * T_ + kc + c16 * 8]);
    }
    CP_COMMIT();
}

__global__ void __launch_bounds__(256, 2)
out_mma2(const bf16* __restrict__ V, const bf16* __restrict__ P,
         const float* __restrict__ rsum, const float* __restrict__ x,
         const float* __restrict__ gamma, float* __restrict__ O)
{
    extern __shared__ __align__(128) char smem[];
    const uint32_t sb = cvta_s(smem);
    float* sInv = reinterpret_cast<float*>(smem + OINV);

    const int b  = blockIdx.z;
    const int n0 = blockIdx.x * 128;   // t
    const int m0 = blockIdx.y * 128;   // c
    const bf16* Vb = V + (size_t)b * C_ * T_;
    const bf16* Pb = P + (size_t)b * T_ * T_;

    const int tid  = threadIdx.x;
    const int lane = tid & 31;
    const int w    = tid >> 5;
    const int wm   = (w >> 2) * 64;
    const int wn   = (w & 3) * 32;

    // fused inv: sum the 8 partials for this block's 128 t values
    if (tid < 128) {
        const float* p = rsum + (size_t)b * 8 * T_ + n0 + tid;
        float s = 0.0f;
        #pragma unroll
        for (int j = 0; j < 8; j++) s += p[j * T_];
        sInv[tid] = 1.0f / s;
    }

    float acc[4][4][4] = {};

    out_issue_chunk(Vb, Pb, m0, n0, 0,  sb, 0, tid);
    out_issue_chunk(Vb, Pb, m0, n0, 64, sb, 1, tid);

    #pragma unroll 1
    for (int ch = 0; ch < 32; ch++) {
        const int buf = ch & 1;
        if (ch < 31) { CP_WAIT(1); } else { CP_WAIT(0); }
        __syncthreads();

        const bf16* sA = reinterpret_cast<const bf16*>(smem + (buf ? OA1 : OA0));
        const bf16* sB = reinterpret_cast<const bf16*>(smem + (buf ? OB1 : OB0));

        #pragma unroll
        for (int kk = 0; kk < 64; kk += 16) {
            uint32_t af[4][4], bf_[4][2];
            #pragma unroll
            for (int mi = 0; mi < 4; mi++) {
                uint32_t a = cvta_s(&sA[(wm + mi * 16 + (lane & 15)) * 72 + kk + (lane >> 4) * 8]);
                ldsm_x4(af[mi], a);
            }
            #pragma unroll
            for (int p = 0; p < 2; p++) {
                uint32_t tmp[4];
                uint32_t a = cvta_s(&sB[(wn + p * 16 + (lane >> 4) * 8 + (lane & 7)) * 72 +
                                        kk + ((lane >> 3) & 1) * 8]);
                ldsm_x4(tmp, a);
                bf_[2 * p][0] = tmp[0]; bf_[2 * p][1] = tmp[1];
                bf_[2 * p + 1][0] = tmp[2]; bf_[2 * p + 1][1] = tmp[3];
            }
            #pragma unroll
            for (int mi = 0; mi < 4; mi++)
                #pragma unroll
                for (int ni = 0; ni < 4; ni++)
                    mma_bf16(acc[mi][ni], af[mi], bf_[ni]);
        }
        __syncthreads();

        if (ch + 2 < 32)
            out_issue_chunk(Vb, Pb, m0, n0, (ch + 2) * 64, sb, buf, tid);
    }

    const float g = gamma[0];
    #pragma unroll
    for (int mi = 0; mi < 4; mi++) {
        int grow = m0 + wm + mi * 16 + (lane >> 2);
        #pragma unroll
        for (int ni = 0; ni < 4; ni++) {
            int lc = wn + ni * 8 + (lane & 3) * 2;
            int gcol = n0 + lc;
            float2 iv = *reinterpret_cast<const float2*>(&sInv[lc]);
            size_t i0 = (size_t)b * C_ * T_ + (size_t)grow * T_ + gcol;
            size_t i1 = (size_t)b * C_ * T_ + (size_t)(grow + 8) * T_ + gcol;
            float2 x0 = *reinterpret_cast<const float2*>(&x[i0]);
            float2 x1 = *reinterpret_cast<const float2*>(&x[i1]);
            *reinterpret_cast<float2*>(&O[i0]) =
                make_float2(g * acc[mi][ni][0] * iv.x + x0.x, g * acc[mi][ni][1] * iv.y + x0.y);
            *reinterpret_cast<float2*>(&O[i1]) =
                make_float2(g * acc[mi][ni][2] * iv.x + x1.x, g * acc[mi][ni][3] * iv.y + x1.y);
        }
    }
}

// ---------------------------------------------------------------------------
// Launch
// ---------------------------------------------------------------------------
extern "C" void kernel_launch(void* const* d_in, const int* in_sizes, int n_in,
                              void* d_out, int out_size)
{
    const float* x     = (const float*)d_in[0];
    const float* wq    = (const float*)d_in[1];
    const float* bq    = (const float*)d_in[2];
    const float* wk    = (const float*)d_in[3];
    const float* bk    = (const float*)d_in[4];
    const float* wv    = (const float*)d_in[5];
    const float* bv    = (const float*)d_in[6];
    const float* gamma = (const float*)d_in[7];
    float* out = (float*)d_out;

    bf16 *xb, *wqb, *wkb, *wvb, *qb, *kb, *vb, *pb;
    float *rs;
    cudaGetSymbolAddress((void**)&xb,  g_xb);
    cudaGetSymbolAddress((void**)&wqb, g_wqb);
    cudaGetSymbolAddress((void**)&wkb, g_wkb);
    cudaGetSymbolAddress((void**)&wvb, g_wvb);
    cudaGetSymbolAddress((void**)&qb,  g_qb);
    cudaGetSymbolAddress((void**)&kb,  g_kb);
    cudaGetSymbolAddress((void**)&vb,  g_vb);
    cudaGetSymbolAddress((void**)&pb,  g_p);
    cudaGetSymbolAddress((void**)&rs,  g_rs);

    cudaFuncSetAttribute(score_exp4, cudaFuncAttributeMaxDynamicSharedMemorySize, SC_SMEM);
    cudaFuncSetAttribute(out_mma2, cudaFuncAttributeMaxDynamicSharedMemorySize, OUT_SMEM);

    // converts
    {
        int n4 = (B_ * C_ * T_) / 4;
        f2b_kernel<<<(n4 + 255) / 256, 256>>>(x, xb, n4);
        int nq4 = (CQ_ * C_) / 4, nv4 = (C_ * C_) / 4;
        int tot = nq4 + nq4 + nv4;
        f2b_w<<<(tot + 255) / 256, 256>>>(wq, wqb, nq4, wk, wkb, nq4, wv, wvb, nv4);
    }

    // all three projections in one launch
    proj_all<<<dim3(T_ / 128, 10, B_), 256>>>(wqb, bq, qb, wkb, bk, kb, wvb, bv, vb, xb);

    // scores + exp + partial row sums (two s-tiles per block, cp.async)
    score_exp4<<<dim3(T_ / 256, T_ / 128, B_), 256, SC_SMEM>>>(qb, kb, pb, rs);

    // output GEMM (inv folded into prologue)
    out_mma2<<<dim3(T_ / 128, C_ / 128, B_), 256, OUT_SMEM>>>(vb, pb, rs, x, gamma, out);
}

// round 11
// speedup vs baseline: 1.1433x; 1.0567x over previous
#include <cuda_runtime.h>
#include <cuda_bf16.h>
#include <cstdint>

using bf16 = __nv_bfloat16;

#define B_  8
#define C_  512
#define T_  2048
#define CQ_ 64
#define MQKV 640           // stacked rows: q 0-63, k 64-127, v 128-639

// ---------------------------------------------------------------------------
// Device-global scratch
// ---------------------------------------------------------------------------
__device__ bf16  g_xb  [B_ * C_ * T_];
__device__ bf16  g_wall[MQKV * C_];              // stacked weights
__device__ float g_ball[MQKV];                   // stacked biases
__device__ bf16  g_qkv [(size_t)B_ * MQKV * T_]; // stacked projections
__device__ bf16  g_p   [(size_t)B_ * T_ * T_];   // unnormalized probs bf16
__device__ float g_rs  [B_ * 8 * T_];            // partial row sums

// ---------------------------------------------------------------------------
// PTX helpers
// ---------------------------------------------------------------------------
__device__ __forceinline__ uint32_t cvta_s(const void* p) {
    return (uint32_t)__cvta_generic_to_shared(p);
}
__device__ __forceinline__ void ldsm_x4(uint32_t* r, uint32_t a) {
    asm volatile("ldmatrix.sync.aligned.m8n8.x4.shared.b16 {%0,%1,%2,%3},[%4];"
                 : "=r"(r[0]), "=r"(r[1]), "=r"(r[2]), "=r"(r[3]) : "r"(a));
}
__device__ __forceinline__ void ldsm_x4t(uint32_t* r, uint32_t a) {
    asm volatile("ldmatrix.sync.aligned.m8n8.x4.trans.shared.b16 {%0,%1,%2,%3},[%4];"
                 : "=r"(r[0]), "=r"(r[1]), "=r"(r[2]), "=r"(r[3]) : "r"(a));
}
__device__ __forceinline__ void mma_bf16(float* c, const uint32_t* a, const uint32_t* b) {
    asm volatile("mma.sync.aligned.m16n8k16.row.col.f32.bf16.bf16.f32 "
                 "{%0,%1,%2,%3},{%4,%5,%6,%7},{%8,%9},{%0,%1,%2,%3};"
                 : "+f"(c[0]), "+f"(c[1]), "+f"(c[2]), "+f"(c[3])
                 : "r"(a[0]), "r"(a[1]), "r"(a[2]), "r"(a[3]), "r"(b[0]), "r"(b[1]));
}
__device__ __forceinline__ void cp16(uint32_t dst, const void* src) {
    asm volatile("cp.async.ca.shared.global [%0], [%1], 16;" :: "r"(dst), "l"(src));
}
#define CP_COMMIT() asm volatile("cp.async.commit_group;" ::: "memory")
#define CP_WAIT(n)  asm volatile("cp.async.wait_group %0;" :: "n"(n) : "memory")

// ---------------------------------------------------------------------------
// One convert kernel: x -> bf16, stacked weights -> bf16, stacked bias copy
// ---------------------------------------------------------------------------
__device__ __forceinline__ void cvt4(const float* in, bf16* out, int i) {
    float4 v = *reinterpret_cast<const float4*>(in + (size_t)i * 4);
    __nv_bfloat162 lo = __floats2bfloat162_rn(v.x, v.y);
    __nv_bfloat162 hi = __floats2bfloat162_rn(v.z, v.w);
    uint2 pk;
    pk.x = *reinterpret_cast<uint32_t*>(&lo);
    pk.y = *reinterpret_cast<uint32_t*>(&hi);
    *reinterpret_cast<uint2*>(out + (size_t)i * 4) = pk;
}
#define NX4  ((B_ * C_ * T_) / 4)                 // 2097152
#define NQ4  ((CQ_ * C_) / 4)                     // 8192
#define NV4  ((C_ * C_) / 4)                      // 65536
#define NTOT (NX4 + 2 * NQ4 + NV4 + MQKV)

__global__ void f2b_all(const float* __restrict__ x,  bf16* __restrict__ xb,
                        const float* __restrict__ wq, const float* __restrict__ wk,
                        const float* __restrict__ wv, bf16* __restrict__ wall,
                        const float* __restrict__ bq, const float* __restrict__ bk,
                        const float* __restrict__ bv, float* __restrict__ ball)
{
    int i = blockIdx.x * blockDim.x + threadIdx.x;
    if (i < NX4)                       { cvt4(x, xb, i); return; }
    i -= NX4;
    if (i < NQ4)                       { cvt4(wq, wall, i); return; }
    i -= NQ4;
    if (i < NQ4)                       { cvt4(wk, wall + CQ_ * C_, i); return; }
    i -= NQ4;
    if (i < NV4)                       { cvt4(wv, wall + 2 * CQ_ * C_, i); return; }
    i -= NV4;
    if (i < MQKV) {
        float v;
        if (i < 64)       v = bq[i];
        else if (i < 128) v = bk[i - 64];
        else              v = bv[i - 128];
        ball[i] = v;
    }
}

// ---------------------------------------------------------------------------
// Stacked QKV projection: QKV[b,m,t] = sum_k Wall[m,k]*X[b,k,t] + ball[m]
// 128(m) x 128(t) tiles, 256 threads = 8 warps (2m x 4n), warp tile 64x32,
// cp.async double-buffered K-chunks of 64. A: [m][k] k-contig (ldsm_x4);
// B: [k][n] n-contig (paired ldsm_x4t, validated in score kernels).
// smem: A[2][128][72] (18432 ea) + B[2][64][136] (17408 ea) = 71680 B
// ---------------------------------------------------------------------------
#define PJ_A0 0u
#define PJ_A1 18432u
#define PJ_B0 36864u
#define PJ_B1 54272u
#define PJ_SMEM 71680u

__device__ __forceinline__ void pj_issue_chunk(const bf16* W, const bf16* Xb,
                                               int m0, int n0, int kc,
                                               uint32_t sb, int buf, int tid)
{
    const uint32_t aoff = buf ? PJ_A1 : PJ_A0;
    const uint32_t boff = buf ? PJ_B1 : PJ_B0;
    // A: 128 rows x 8 uint4 = 1024, 4/thread
    #pragma unroll
    for (int j = 0; j < 4; j++) {
        int u = tid + j * 256;
        int row = u >> 3, c16 = u & 7;
        cp16(sb + aoff + (uint32_t)(row * 144 + c16 * 16),
             &W[(size_t)(m0 + row) * C_ + kc + c16 * 8]);
    }
    // B: 64 rows x 16 uint4 = 1024, 4/thread
    #pragma unroll
    for (int j = 0; j < 4; j++) {
        int u = tid + j * 256;
        int row = u >> 4, c16 = u & 15;
        cp16(sb + boff + (uint32_t)(row * 272 + c16 * 16),
             &Xb[(size_t)(kc + row) * T_ + n0 + c16 * 8]);
    }
    CP_COMMIT();
}

__global__ void __launch_bounds__(256, 2)
proj_stk(const bf16* __restrict__ Wall, const float* __restrict__ ball,
         const bf16* __restrict__ X, bf16* __restrict__ QKV)
{
    extern __shared__ __align__(128) char smem[];
    const uint32_t sb = cvta_s(smem);

    const int b  = blockIdx.z;
    const int n0 = blockIdx.x * 128;   // t
    const int m0 = blockIdx.y * 128;   // stacked row
    const bf16* Xb = X + (size_t)b * C_ * T_;
    bf16* Ob = QKV + (size_t)b * MQKV * T_;

    const int tid  = threadIdx.x;
    const int lane = tid & 31;
    const int w    = tid >> 5;
    const int wm   = (w >> 2) * 64;
    const int wn   = (w & 3) * 32;

    float acc[4][4][4] = {};

    pj_issue_chunk(Wall, Xb, m0, n0, 0,  sb, 0, tid);
    pj_issue_chunk(Wall, Xb, m0, n0, 64, sb, 1, tid);

    #pragma unroll 1
    for (int ch = 0; ch < 8; ch++) {
        const int buf = ch & 1;
        if (ch < 7) { CP_WAIT(1); } else { CP_WAIT(0); }
        __syncthreads();

        const bf16* sA = reinterpret_cast<const bf16*>(smem + (buf ? PJ_A1 : PJ_A0));
        const bf16* sB = reinterpret_cast<const bf16*>(smem + (buf ? PJ_B1 : PJ_B0));

        #pragma unroll
        for (int kk = 0; kk < 64; kk += 16) {
            uint32_t af[4][4], bf_[4][2];
            #pragma unroll
            for (int mi = 0; mi < 4; mi++) {
                uint32_t a = cvta_s(&sA[(wm + mi * 16 + (lane & 15)) * 72 + kk + (lane >> 4) * 8]);
                ldsm_x4(af[mi], a);
            }
            #pragma unroll
            for (int p = 0; p < 2; p++) {
                uint32_t tmp[4];
                uint32_t a = cvta_s(&sB[(kk + ((lane >> 3) & 1) * 8 + (lane & 7)) * 136 +
                                        wn + p * 16 + (lane >> 4) * 8]);
                ldsm_x4t(tmp, a);
                bf_[2 * p][0] = tmp[0]; bf_[2 * p][1] = tmp[1];
                bf_[2 * p + 1][0] = tmp[2]; bf_[2 * p + 1][1] = tmp[3];
            }
            #pragma unroll
            for (int mi = 0; mi < 4; mi++)
                #pragma unroll
                for (int ni = 0; ni < 4; ni++)
                    mma_bf16(acc[mi][ni], af[mi], bf_[ni]);
        }
        __syncthreads();

        if (ch + 2 < 8)
            pj_issue_chunk(Wall, Xb, m0, n0, (ch + 2) * 64, sb, buf, tid);
    }

    #pragma unroll
    for (int mi = 0; mi < 4; mi++) {
        int grow = m0 + wm + mi * 16 + (lane >> 2);
        float bv0 = ball[grow];
        float bv1 = ball[grow + 8];
        #pragma unroll
        for (int ni = 0; ni < 4; ni++) {
            int gcol = n0 + wn + ni * 8 + (lane & 3) * 2;
            __nv_bfloat162 v0 = __floats2bfloat162_rn(acc[mi][ni][0] + bv0, acc[mi][ni][1] + bv0);
            __nv_bfloat162 v1 = __floats2bfloat162_rn(acc[mi][ni][2] + bv1, acc[mi][ni][3] + bv1);
            *reinterpret_cast<__nv_bfloat162*>(&Ob[(size_t)grow * T_ + gcol]) = v0;
            *reinterpret_cast<__nv_bfloat162*>(&Ob[(size_t)(grow + 8) * T_ + gcol]) = v1;
        }
    }
}

// ---------------------------------------------------------------------------
// Scores + exp (round-10 winner): 128t x 256s per block, Q loaded once,
// cp.async prefetch of second K tile.
// ---------------------------------------------------------------------------
#define SC_Q    0u
#define SC_K0   17408u
#define SC_K1   34816u
#define SC_STG  52224u
#define SC_RED  87040u
#define SC_SMEM 89088u

__global__ void __launch_bounds__(256, 2)
score_exp4(const bf16* __restrict__ QKV, bf16* __restrict__ P,
           float* __restrict__ partial)
{
    extern __shared__ __align__(16) char sm[];
    const uint32_t sb = cvta_s(sm);
    bf16*  sQ  = reinterpret_cast<bf16*>(sm + SC_Q);
    bf16*  stg = reinterpret_cast<bf16*>(sm + SC_STG);
    float* red = reinterpret_cast<float*>(sm + SC_RED);

    const int b   = blockIdx.z;
    const int s0g = blockIdx.x * 256;
    const int t0  = blockIdx.y * 128;
    const bf16* Qb = QKV + (size_t)b * MQKV * T_;          // q rows 0-63
    const bf16* Kb = Qb + (size_t)CQ_ * T_;                // k rows 64-127

    const int tid  = threadIdx.x;
    const int lane = tid & 31;
    const int w    = tid >> 5;
    const int wm   = (w >> 2) * 64;
    const int wn   = (w & 3) * 32;

    #pragma unroll
    for (int j = 0; j < 4; j++) {
        int u = tid + j * 256;
        int r = u >> 4, c16 = u & 15;
        cp16(sb + SC_Q + (uint32_t)(r * 272 + c16 * 16),
             &Qb[(size_t)r * T_ + t0 + c16 * 8]);
        cp16(sb + SC_K0 + (uint32_t)(r * 272 + c16 * 16),
             &Kb[(size_t)r * T_ + s0g + c16 * 8]);
    }
    CP_COMMIT();
    #pragma unroll
    for (int j = 0; j < 4; j++) {
        int u = tid + j * 256;
        int r = u >> 4, c16 = u & 15;
        cp16(sb + SC_K1 + (uint32_t)(r * 272 + c16 * 16),
             &Kb[(size_t)r * T_ + s0g + 128 + c16 * 8]);
    }
    CP_COMMIT();

    float rs[4][2] = {};
    bf16* Pb = P + (size_t)b * T_ * T_;

    #pragma unroll 1
    for (int it = 0; it < 2; it++) {
        if (it == 0) { CP_WAIT(1); } else { CP_WAIT(0); }
        __syncthreads();

        const bf16* sK = reinterpret_cast<const bf16*>(sm + (it ? SC_K1 : SC_K0));

        float acc[4][4][4] = {};
        #pragma unroll
        for (int kk = 0; kk < 64; kk += 16) {
            uint32_t af[4][4], bf_[4][2];
            const int g = lane >> 3;
            #pragma unroll
            for (int mi = 0; mi < 4; mi++) {
                uint32_t a = cvta_s(&sQ[(kk + (g >> 1) * 8 + (lane & 7)) * 136 +
                                        wm + mi * 16 + (g & 1) * 8]);
                ldsm_x4t(af[mi], a);
            }
            #pragma unroll
            for (int p = 0; p < 2; p++) {
                uint32_t tmp[4];
                uint32_t a = cvta_s(&sK[(kk + ((lane >> 3) & 1) * 8 + (lane & 7)) * 136 +
                                        wn + p * 16 + (lane >> 4) * 8]);
                ldsm_x4t(tmp, a);
                bf_[2 * p][0] = tmp[0]; bf_[2 * p][1] = tmp[1];
                bf_[2 * p + 1][0] = tmp[2]; bf_[2 * p + 1][1] = tmp[3];
            }
            #pragma unroll
            for (int mi = 0; mi < 4; mi++)
                #pragma unroll
                for (int ni = 0; ni < 4; ni++)
                    mma_bf16(acc[mi][ni], af[mi], bf_[ni]);
        }

        #pragma unroll
        for (int mi = 0; mi < 4; mi++) {
            int r0 = wm + mi * 16 + (lane >> 2);
            #pragma unroll
            for (int ni = 0; ni < 4; ni++) {
                float p0 = __expf(acc[mi][ni][0]);
                float p1 = __expf(acc[mi][ni][1]);
                float p2 = __expf(acc[mi][ni][2]);
                float p3 = __expf(acc[mi][ni][3]);
                rs[mi][0] += p0 + p1;
                rs[mi][1] += p2 + p3;
                int cc = wn + ni * 8 + (lane & 3) * 2;
                __nv_bfloat162 lo = __floats2bfloat162_rn(p0, p1);
                __nv_bfloat162 hi = __floats2bfloat162_rn(p2, p3);
                *reinterpret_cast<__nv_bfloat162*>(&stg[r0 * 136 + cc]) = lo;
                *reinterpret_cast<__nv_bfloat162*>(&stg[(r0 + 8) * 136 + cc]) = hi;
            }
        }
        __syncthreads();

        const int sg = s0g + it * 128;
        #pragma unroll
        for (int j = 0; j < 8; j++) {
            int u = tid + j * 256;
            int row = u >> 4, c = (u & 15) * 8;
            *reinterpret_cast<uint4*>(&Pb[(size_t)(t0 + row) * T_ + sg + c]) =
                *reinterpret_cast<const uint4*>(&stg[row * 136 + c]);
        }
    }

    #pragma unroll
    for (int mi = 0; mi < 4; mi++)
        #pragma unroll
        for (int h = 0; h < 2; h++) {
            float v = rs[mi][h];
            v += __shfl_xor_sync(0xffffffffu, v, 1);
            v += __shfl_xor_sync(0xffffffffu, v, 2);
            if ((lane & 3) == 0)
                red[(w & 3) * 128 + wm + mi * 16 + h * 8 + (lane >> 2)] = v;
        }
    __syncthreads();
    if (tid < 128) {
        float tot = red[tid] + red[128 + tid] + red[256 + tid] + red[384 + tid];
        partial[((size_t)b * 8 + blockIdx.x) * T_ + t0 + tid] = tot;
    }
}

// ---------------------------------------------------------------------------
// Output GEMM (round-10 winner) with fused inv prologue.
// ---------------------------------------------------------------------------
#define OA0 0u
#define OA1 18432u
#define OB0 36864u
#define OB1 55296u
#define OINV 73728u
#define OUT_SMEM 74240u

__device__ __forceinline__ void out_issue_chunk(const bf16* Vb, const bf16* Pb,
                                                int m0, int n0, int kc,
                                                uint32_t sb, int buf, int tid)
{
    const uint32_t aoff = buf ? OA1 : OA0;
    const uint32_t boff = buf ? OB1 : OB0;
    #pragma unroll
    for (int j = 0; j < 4; j++) {
        int u = tid + j * 256;
        int row = u >> 3, c16 = u & 7;
        cp16(sb + aoff + (uint32_t)(row * 144 + c16 * 16),
             &Vb[(size_t)(m0 + row) * T_ + kc + c16 * 8]);
    }
    #pragma unroll
    for (int j = 0; j < 4; j++) {
        int u = tid + j * 256;
        int row = u >> 3, c16 = u & 7;
        cp16(sb + boff + (uint32_t)(row * 144 + c16 * 16),
             &Pb[(size_t)(n0 + row) * T_ + kc + c16 * 8]);
    }
    CP_COMMIT();
}

__global__ void __launch_bounds__(256, 2)
out_mma2(const bf16* __restrict__ QKV, const bf16* __restrict__ P,
         const float* __restrict__ rsum, const float* __restrict__ x,
         const float* __restrict__ gamma, float* __restrict__ O)
{
    extern __shared__ __align__(128) char smem[];
    const uint32_t sb = cvta_s(smem);
    float* sInv = reinterpret_cast<float*>(smem + OINV);

    const int b  = blockIdx.z;
    const int n0 = blockIdx.x * 128;   // t
    const int m0 = blockIdx.y * 128;   // c
    const bf16* Vb = QKV + (size_t)b * MQKV * T_ + (size_t)(2 * CQ_) * T_;  // v rows 128-639
    const bf16* Pb = P + (size_t)b * T_ * T_;

    const int tid  = threadIdx.x;
    const int lane = tid & 31;
    const int w    = tid >> 5;
    const int wm   = (w >> 2) * 64;
    const int wn   = (w & 3) * 32;

    if (tid < 128) {
        const float* p = rsum + (size_t)b * 8 * T_ + n0 + tid;
        float s = 0.0f;
        #pragma unroll
        for (int j = 0; j < 8; j++) s += p[j * T_];
        sInv[tid] = 1.0f / s;
    }

    float acc[4][4][4] = {};

    out_issue_chunk(Vb, Pb, m0, n0, 0,  sb, 0, tid);
    out_issue_chunk(Vb, Pb, m0, n0, 64, sb, 1, tid);

    #pragma unroll 1
    for (int ch = 0; ch < 32; ch++) {
        const int buf = ch & 1;
        if (ch < 31) { CP_WAIT(1); } else { CP_WAIT(0); }
        __syncthreads();

        const bf16* sA = reinterpret_cast<const bf16*>(smem + (buf ? OA1 : OA0));
        const bf16* sB = reinterpret_cast<const bf16*>(smem + (buf ? OB1 : OB0));

        #pragma unroll
        for (int kk = 0; kk < 64; kk += 16) {
            uint32_t af[4][4], bf_[4][2];
            #pragma unroll
            for (int mi = 0; mi < 4; mi++) {
                uint32_t a = cvta_s(&sA[(wm + mi * 16 + (lane & 15)) * 72 + kk + (lane >> 4) * 8]);
                ldsm_x4(af[mi], a);
            }
            #pragma unroll
            for (int p = 0; p < 2; p++) {
                uint32_t tmp[4];
                uint32_t a = cvta_s(&sB[(wn + p * 16 + (lane >> 4) * 8 + (lane & 7)) * 72 +
                                        kk + ((lane >> 3) & 1) * 8]);
                ldsm_x4(tmp, a);
                bf_[2 * p][0] = tmp[0]; bf_[2 * p][1] = tmp[1];
                bf_[2 * p + 1][0] = tmp[2]; bf_[2 * p + 1][1] = tmp[3];
            }
            #pragma unroll
            for (int mi = 0; mi < 4; mi++)
                #pragma unroll
                for (int ni = 0; ni < 4; ni++)
                    mma_bf16(acc[mi][ni], af[mi], bf_[ni]);
        }
        __syncthreads();

        if (ch + 2 < 32)
            out_issue_chunk(Vb, Pb, m0, n0, (ch + 2) * 64, sb, buf, tid);
    }

    const float g = gamma[0];
    #pragma unroll
    for (int mi = 0; mi < 4; mi++) {
        int grow = m0 + wm + mi * 16 + (lane >> 2);
        #pragma unroll
        for (int ni = 0; ni < 4; ni++) {
            int lc = wn + ni * 8 + (lane & 3) * 2;
            int gcol = n0 + lc;
            float2 iv = *reinterpret_cast<const float2*>(&sInv[lc]);
            size_t i0 = (size_t)b * C_ * T_ + (size_t)grow * T_ + gcol;
            size_t i1 = (size_t)b * C_ * T_ + (size_t)(grow + 8) * T_ + gcol;
            float2 x0 = *reinterpret_cast<const float2*>(&x[i0]);
            float2 x1 = *reinterpret_cast<const float2*>(&x[i1]);
            *reinterpret_cast<float2*>(&O[i0]) =
                make_float2(g * acc[mi][ni][0] * iv.x + x0.x, g * acc[mi][ni][1] * iv.y + x0.y);
            *reinterpret_cast<float2*>(&O[i1]) =
                make_float2(g * acc[mi][ni][2] * iv.x + x1.x, g * acc[mi][ni][3] * iv.y + x1.y);
        }
    }
}

// ---------------------------------------------------------------------------
// Launch
// ---------------------------------------------------------------------------
extern "C" void kernel_launch(void* const* d_in, const int* in_sizes, int n_in,
                              void* d_out, int out_size)
{
    const float* x     = (const float*)d_in[0];
    const float* wq    = (const float*)d_in[1];
    const float* bq    = (const float*)d_in[2];
    const float* wk    = (const float*)d_in[3];
    const float* bk    = (const float*)d_in[4];
    const float* wv    = (const float*)d_in[5];
    const float* bv    = (const float*)d_in[6];
    const float* gamma = (const float*)d_in[7];
    float* out = (float*)d_out;

    bf16 *xb, *wall, *qkv, *pb;
    float *ball, *rs;
    cudaGetSymbolAddress((void**)&xb,   g_xb);
    cudaGetSymbolAddress((void**)&wall, g_wall);
    cudaGetSymbolAddress((void**)&ball, g_ball);
    cudaGetSymbolAddress((void**)&qkv,  g_qkv);
    cudaGetSymbolAddress((void**)&pb,   g_p);
    cudaGetSymbolAddress((void**)&rs,   g_rs);

    cudaFuncSetAttribute(proj_stk,   cudaFuncAttributeMaxDynamicSharedMemorySize, PJ_SMEM);
    cudaFuncSetAttribute(score_exp4, cudaFuncAttributeMaxDynamicSharedMemorySize, SC_SMEM);
    cudaFuncSetAttribute(out_mma2,   cudaFuncAttributeMaxDynamicSharedMemorySize, OUT_SMEM);

    // single convert launch (x + stacked weights + stacked bias)
    f2b_all<<<(NTOT + 255) / 256, 256>>>(x, xb, wq, wk, wv, wall, bq, bk, bv, ball);

    // stacked QKV projection (M=640)
    proj_stk<<<dim3(T_ / 128, MQKV / 128, B_), 256, PJ_SMEM>>>(wall, ball, xb, qkv);

    // scores + exp + partial row sums
    score_exp4<<<dim3(T_ / 256, T_ / 128, B_), 256, SC_SMEM>>>(qkv, pb, rs);

    // output GEMM (inv folded into prologue)
    out_mma2<<<dim3(T_ / 128, C_ / 128, B_), 256, OUT_SMEM>>>(qkv, pb, rs, x, gamma, out);
}

// round 12
// speedup vs baseline: 1.1602x; 1.0148x over previous
#include <cuda_runtime.h>
#include <cuda_bf16.h>
#include <cstdint>

using bf16 = __nv_bfloat16;

#define B_  8
#define C_  512
#define T_  2048
#define CQ_ 64
#define MQKV 640           // stacked rows: q 0-63, k 64-127, v 128-639

// ---------------------------------------------------------------------------
// Device-global scratch
// ---------------------------------------------------------------------------
__device__ bf16  g_xb  [B_ * C_ * T_];
__device__ bf16  g_wall[MQKV * C_];
__device__ float g_ball[MQKV];
__device__ bf16  g_qkv [(size_t)B_ * MQKV * T_];
__device__ bf16  g_p   [(size_t)B_ * T_ * T_];
__device__ float g_rs  [B_ * 8 * T_];

// ---------------------------------------------------------------------------
// PTX helpers
// ---------------------------------------------------------------------------
__device__ __forceinline__ uint32_t cvta_s(const void* p) {
    return (uint32_t)__cvta_generic_to_shared(p);
}
__device__ __forceinline__ void ldsm_x4(uint32_t* r, uint32_t a) {
    asm volatile("ldmatrix.sync.aligned.m8n8.x4.shared.b16 {%0,%1,%2,%3},[%4];"
                 : "=r"(r[0]), "=r"(r[1]), "=r"(r[2]), "=r"(r[3]) : "r"(a));
}
__device__ __forceinline__ void ldsm_x4t(uint32_t* r, uint32_t a) {
    asm volatile("ldmatrix.sync.aligned.m8n8.x4.trans.shared.b16 {%0,%1,%2,%3},[%4];"
                 : "=r"(r[0]), "=r"(r[1]), "=r"(r[2]), "=r"(r[3]) : "r"(a));
}
__device__ __forceinline__ void mma_bf16(float* c, const uint32_t* a, const uint32_t* b) {
    asm volatile("mma.sync.aligned.m16n8k16.row.col.f32.bf16.bf16.f32 "
                 "{%0,%1,%2,%3},{%4,%5,%6,%7},{%8,%9},{%0,%1,%2,%3};"
                 : "+f"(c[0]), "+f"(c[1]), "+f"(c[2]), "+f"(c[3])
                 : "r"(a[0]), "r"(a[1]), "r"(a[2]), "r"(a[3]), "r"(b[0]), "r"(b[1]));
}
__device__ __forceinline__ void cp16(uint32_t dst, const void* src) {
    asm volatile("cp.async.ca.shared.global [%0], [%1], 16;" :: "r"(dst), "l"(src));
}
#define CP_COMMIT() asm volatile("cp.async.commit_group;" ::: "memory")
#define CP_WAIT(n)  asm volatile("cp.async.wait_group %0;" :: "n"(n) : "memory")

// ---------------------------------------------------------------------------
// Converts (validated round 11)
// ---------------------------------------------------------------------------
__device__ __forceinline__ void cvt4(const float* in, bf16* out, int i) {
    float4 v = *reinterpret_cast<const float4*>(in + (size_t)i * 4);
    __nv_bfloat162 lo = __floats2bfloat162_rn(v.x, v.y);
    __nv_bfloat162 hi = __floats2bfloat162_rn(v.z, v.w);
    uint2 pk;
    pk.x = *reinterpret_cast<uint32_t*>(&lo);
    pk.y = *reinterpret_cast<uint32_t*>(&hi);
    *reinterpret_cast<uint2*>(out + (size_t)i * 4) = pk;
}
#define NX4  ((B_ * C_ * T_) / 4)
#define NQ4  ((CQ_ * C_) / 4)
#define NV4  ((C_ * C_) / 4)
#define NTOT (NX4 + 2 * NQ4 + NV4 + MQKV)

__global__ void f2b_all(const float* __restrict__ x,  bf16* __restrict__ xb,
                        const float* __restrict__ wq, const float* __restrict__ wk,
                        const float* __restrict__ wv, bf16* __restrict__ wall,
                        const float* __restrict__ bq, const float* __restrict__ bk,
                        const float* __restrict__ bv, float* __restrict__ ball)
{
    int i = blockIdx.x * blockDim.x + threadIdx.x;
    if (i < NX4)                       { cvt4(x, xb, i); return; }
    i -= NX4;
    if (i < NQ4)                       { cvt4(wq, wall, i); return; }
    i -= NQ4;
    if (i < NQ4)                       { cvt4(wk, wall + CQ_ * C_, i); return; }
    i -= NQ4;
    if (i < NV4)                       { cvt4(wv, wall + 2 * CQ_ * C_, i); return; }
    i -= NV4;
    if (i < MQKV) {
        float v;
        if (i < 64)       v = bq[i];
        else if (i < 128) v = bk[i - 64];
        else              v = bv[i - 128];
        ball[i] = v;
    }
}

// ---------------------------------------------------------------------------
// Stacked QKV projection (validated round 11)
// ---------------------------------------------------------------------------
#define PJ_A0 0u
#define PJ_A1 18432u
#define PJ_B0 36864u
#define PJ_B1 54272u
#define PJ_SMEM 71680u

__device__ __forceinline__ void pj_issue_chunk(const bf16* W, const bf16* Xb,
                                               int m0, int n0, int kc,
                                               uint32_t sb, int buf, int tid)
{
    const uint32_t aoff = buf ? PJ_A1 : PJ_A0;
    const uint32_t boff = buf ? PJ_B1 : PJ_B0;
    #pragma unroll
    for (int j = 0; j < 4; j++) {
        int u = tid + j * 256;
        int row = u >> 3, c16 = u & 7;
        cp16(sb + aoff + (uint32_t)(row * 144 + c16 * 16),
             &W[(size_t)(m0 + row) * C_ + kc + c16 * 8]);
    }
    #pragma unroll
    for (int j = 0; j < 4; j++) {
        int u = tid + j * 256;
        int row = u >> 4, c16 = u & 15;
        cp16(sb + boff + (uint32_t)(row * 272 + c16 * 16),
             &Xb[(size_t)(kc + row) * T_ + n0 + c16 * 8]);
    }
    CP_COMMIT();
}

__global__ void __launch_bounds__(256, 2)
proj_stk(const bf16* __restrict__ Wall, const float* __restrict__ ball,
         const bf16* __restrict__ X, bf16* __restrict__ QKV)
{
    extern __shared__ __align__(128) char smem[];
    const uint32_t sb = cvta_s(smem);

    const int b  = blockIdx.z;
    const int n0 = blockIdx.x * 128;
    const int m0 = blockIdx.y * 128;
    const bf16* Xb = X + (size_t)b * C_ * T_;
    bf16* Ob = QKV + (size_t)b * MQKV * T_;

    const int tid  = threadIdx.x;
    const int lane = tid & 31;
    const int w    = tid >> 5;
    const int wm   = (w >> 2) * 64;
    const int wn   = (w & 3) * 32;

    float acc[4][4][4] = {};

    pj_issue_chunk(Wall, Xb, m0, n0, 0,  sb, 0, tid);
    pj_issue_chunk(Wall, Xb, m0, n0, 64, sb, 1, tid);

    #pragma unroll 1
    for (int ch = 0; ch < 8; ch++) {
        const int buf = ch & 1;
        if (ch < 7) { CP_WAIT(1); } else { CP_WAIT(0); }
        __syncthreads();

        const bf16* sA = reinterpret_cast<const bf16*>(smem + (buf ? PJ_A1 : PJ_A0));
        const bf16* sB = reinterpret_cast<const bf16*>(smem + (buf ? PJ_B1 : PJ_B0));

        #pragma unroll
        for (int kk = 0; kk < 64; kk += 16) {
            uint32_t af[4][4], bf_[4][2];
            #pragma unroll
            for (int mi = 0; mi < 4; mi++) {
                uint32_t a = cvta_s(&sA[(wm + mi * 16 + (lane & 15)) * 72 + kk + (lane >> 4) * 8]);
                ldsm_x4(af[mi], a);
            }
            #pragma unroll
            for (int p = 0; p < 2; p++) {
                uint32_t tmp[4];
                uint32_t a = cvta_s(&sB[(kk + ((lane >> 3) & 1) * 8 + (lane & 7)) * 136 +
                                        wn + p * 16 + (lane >> 4) * 8]);
                ldsm_x4t(tmp, a);
                bf_[2 * p][0] = tmp[0]; bf_[2 * p][1] = tmp[1];
                bf_[2 * p + 1][0] = tmp[2]; bf_[2 * p + 1][1] = tmp[3];
            }
            #pragma unroll
            for (int mi = 0; mi < 4; mi++)
                #pragma unroll
                for (int ni = 0; ni < 4; ni++)
                    mma_bf16(acc[mi][ni], af[mi], bf_[ni]);
        }
        __syncthreads();

        if (ch + 2 < 8)
            pj_issue_chunk(Wall, Xb, m0, n0, (ch + 2) * 64, sb, buf, tid);
    }

    #pragma unroll
    for (int mi = 0; mi < 4; mi++) {
        int grow = m0 + wm + mi * 16 + (lane >> 2);
        float bv0 = ball[grow];
        float bv1 = ball[grow + 8];
        #pragma unroll
        for (int ni = 0; ni < 4; ni++) {
            int gcol = n0 + wn + ni * 8 + (lane & 3) * 2;
            __nv_bfloat162 v0 = __floats2bfloat162_rn(acc[mi][ni][0] + bv0, acc[mi][ni][1] + bv0);
            __nv_bfloat162 v1 = __floats2bfloat162_rn(acc[mi][ni][2] + bv1, acc[mi][ni][3] + bv1);
            *reinterpret_cast<__nv_bfloat162*>(&Ob[(size_t)grow * T_ + gcol]) = v0;
            *reinterpret_cast<__nv_bfloat162*>(&Ob[(size_t)(grow + 8) * T_ + gcol]) = v1;
        }
    }
}

// ---------------------------------------------------------------------------
// Scores + exp (validated round 10/11)
// ---------------------------------------------------------------------------
#define SC_Q    0u
#define SC_K0   17408u
#define SC_K1   34816u
#define SC_STG  52224u
#define SC_RED  87040u
#define SC_SMEM 89088u

__global__ void __launch_bounds__(256, 2)
score_exp4(const bf16* __restrict__ QKV, bf16* __restrict__ P,
           float* __restrict__ partial)
{
    extern __shared__ __align__(16) char sm[];
    const uint32_t sb = cvta_s(sm);
    bf16*  sQ  = reinterpret_cast<bf16*>(sm + SC_Q);
    bf16*  stg = reinterpret_cast<bf16*>(sm + SC_STG);
    float* red = reinterpret_cast<float*>(sm + SC_RED);

    const int b   = blockIdx.z;
    const int s0g = blockIdx.x * 256;
    const int t0  = blockIdx.y * 128;
    const bf16* Qb = QKV + (size_t)b * MQKV * T_;
    const bf16* Kb = Qb + (size_t)CQ_ * T_;

    const int tid  = threadIdx.x;
    const int lane = tid & 31;
    const int w    = tid >> 5;
    const int wm   = (w >> 2) * 64;
    const int wn   = (w & 3) * 32;

    #pragma unroll
    for (int j = 0; j < 4; j++) {
        int u = tid + j * 256;
        int r = u >> 4, c16 = u & 15;
        cp16(sb + SC_Q + (uint32_t)(r * 272 + c16 * 16),
             &Qb[(size_t)r * T_ + t0 + c16 * 8]);
        cp16(sb + SC_K0 + (uint32_t)(r * 272 + c16 * 16),
             &Kb[(size_t)r * T_ + s0g + c16 * 8]);
    }
    CP_COMMIT();
    #pragma unroll
    for (int j = 0; j < 4; j++) {
        int u = tid + j * 256;
        int r = u >> 4, c16 = u & 15;
        cp16(sb + SC_K1 + (uint32_t)(r * 272 + c16 * 16),
             &Kb[(size_t)r * T_ + s0g + 128 + c16 * 8]);
    }
    CP_COMMIT();

    float rs[4][2] = {};
    bf16* Pb = P + (size_t)b * T_ * T_;

    #pragma unroll 1
    for (int it = 0; it < 2; it++) {
        if (it == 0) { CP_WAIT(1); } else { CP_WAIT(0); }
        __syncthreads();

        const bf16* sK = reinterpret_cast<const bf16*>(sm + (it ? SC_K1 : SC_K0));

        float acc[4][4][4] = {};
        #pragma unroll
        for (int kk = 0; kk < 64; kk += 16) {
            uint32_t af[4][4], bf_[4][2];
            const int g = lane >> 3;
            #pragma unroll
            for (int mi = 0; mi < 4; mi++) {
                uint32_t a = cvta_s(&sQ[(kk + (g >> 1) * 8 + (lane & 7)) * 136 +
                                        wm + mi * 16 + (g & 1) * 8]);
                ldsm_x4t(af[mi], a);
            }
            #pragma unroll
            for (int p = 0; p < 2; p++) {
                uint32_t tmp[4];
                uint32_t a = cvta_s(&sK[(kk + ((lane >> 3) & 1) * 8 + (lane & 7)) * 136 +
                                        wn + p * 16 + (lane >> 4) * 8]);
                ldsm_x4t(tmp, a);
                bf_[2 * p][0] = tmp[0]; bf_[2 * p][1] = tmp[1];
                bf_[2 * p + 1][0] = tmp[2]; bf_[2 * p + 1][1] = tmp[3];
            }
            #pragma unroll
            for (int mi = 0; mi < 4; mi++)
                #pragma unroll
                for (int ni = 0; ni < 4; ni++)
                    mma_bf16(acc[mi][ni], af[mi], bf_[ni]);
        }

        #pragma unroll
        for (int mi = 0; mi < 4; mi++) {
            int r0 = wm + mi * 16 + (lane >> 2);
            #pragma unroll
            for (int ni = 0; ni < 4; ni++) {
                float p0 = __expf(acc[mi][ni][0]);
                float p1 = __expf(acc[mi][ni][1]);
                float p2 = __expf(acc[mi][ni][2]);
                float p3 = __expf(acc[mi][ni][3]);
                rs[mi][0] += p0 + p1;
                rs[mi][1] += p2 + p3;
                int cc = wn + ni * 8 + (lane & 3) * 2;
                __nv_bfloat162 lo = __floats2bfloat162_rn(p0, p1);
                __nv_bfloat162 hi = __floats2bfloat162_rn(p2, p3);
                *reinterpret_cast<__nv_bfloat162*>(&stg[r0 * 136 + cc]) = lo;
                *reinterpret_cast<__nv_bfloat162*>(&stg[(r0 + 8) * 136 + cc]) = hi;
            }
        }
        __syncthreads();

        const int sg = s0g + it * 128;
        #pragma unroll
        for (int j = 0; j < 8; j++) {
            int u = tid + j * 256;
            int row = u >> 4, c = (u & 15) * 8;
            *reinterpret_cast<uint4*>(&Pb[(size_t)(t0 + row) * T_ + sg + c]) =
                *reinterpret_cast<const uint4*>(&stg[row * 136 + c]);
        }
    }

    #pragma unroll
    for (int mi = 0; mi < 4; mi++)
        #pragma unroll
        for (int h = 0; h < 2; h++) {
            float v = rs[mi][h];
            v += __shfl_xor_sync(0xffffffffu, v, 1);
            v += __shfl_xor_sync(0xffffffffu, v, 2);
            if ((lane & 3) == 0)
                red[(w & 3) * 128 + wm + mi * 16 + h * 8 + (lane >> 2)] = v;
        }
    __syncthreads();
    if (tid < 128) {
        float tot = red[tid] + red[128 + tid] + red[256 + tid] + red[384 + tid];
        partial[((size_t)b * 8 + blockIdx.x) * T_ + t0 + tid] = tot;
    }
}

// ---------------------------------------------------------------------------
// Output GEMM v5: 128x128 block tile, 128 threads = 4 warps (2m x 2n),
// warp tile 64x64 — halves smem bytes per MMA (128 B/MMA vs 192).
// cp.async double-buffered, fused inv prologue.
// ---------------------------------------------------------------------------
#define OA0 0u
#define OA1 18432u
#define OB0 36864u
#define OB1 55296u
#define OINV 73728u
#define OUT_SMEM 74240u

__device__ __forceinline__ void out_issue_chunk(const bf16* Vb, const bf16* Pb,
                                                int m0, int n0, int kc,
                                                uint32_t sb, int buf, int tid)
{
    const uint32_t aoff = buf ? OA1 : OA0;
    const uint32_t boff = buf ? OB1 : OB0;
    // 1024 uint4 per tile, 128 threads -> 8/thread
    #pragma unroll
    for (int j = 0; j < 8; j++) {
        int u = tid + j * 128;
        int row = u >> 3, c16 = u & 7;
        cp16(sb + aoff + (uint32_t)(row * 144 + c16 * 16),
             &Vb[(size_t)(m0 + row) * T_ + kc + c16 * 8]);
    }
    #pragma unroll
    for (int j = 0; j < 8; j++) {
        int u = tid + j * 128;
        int row = u >> 3, c16 = u & 7;
        cp16(sb + boff + (uint32_t)(row * 144 + c16 * 16),
             &Pb[(size_t)(n0 + row) * T_ + kc + c16 * 8]);
    }
    CP_COMMIT();
}

__global__ void __launch_bounds__(128, 2)
out_mma5(const bf16* __restrict__ QKV, const bf16* __restrict__ P,
         const float* __restrict__ rsum, const float* __restrict__ x,
         const float* __restrict__ gamma, float* __restrict__ O)
{
    extern __shared__ __align__(128) char smem[];
    const uint32_t sb = cvta_s(smem);
    float* sInv = reinterpret_cast<float*>(smem + OINV);

    const int b  = blockIdx.z;
    const int n0 = blockIdx.x * 128;   // t
    const int m0 = blockIdx.y * 128;   // c
    const bf16* Vb = QKV + (size_t)b * MQKV * T_ + (size_t)(2 * CQ_) * T_;
    const bf16* Pb = P + (size_t)b * T_ * T_;

    const int tid  = threadIdx.x;
    const int lane = tid & 31;
    const int w    = tid >> 5;
    const int wm   = (w >> 1) * 64;    // c warp offset (0 or 64)
    const int wn   = (w & 1) * 64;     // t warp offset (0 or 64)

    // fused inv: all 128 threads
    {
        const float* p = rsum + (size_t)b * 8 * T_ + n0 + tid;
        float s = 0.0f;
        #pragma unroll
        for (int j = 0; j < 8; j++) s += p[j * T_];
        sInv[tid] = 1.0f / s;
    }

    float acc[4][8][4] = {};

    out_issue_chunk(Vb, Pb, m0, n0, 0,  sb, 0, tid);
    out_issue_chunk(Vb, Pb, m0, n0, 64, sb, 1, tid);

    #pragma unroll 1
    for (int ch = 0; ch < 32; ch++) {
        const int buf = ch & 1;
        if (ch < 31) { CP_WAIT(1); } else { CP_WAIT(0); }
        __syncthreads();

        const bf16* sA = reinterpret_cast<const bf16*>(smem + (buf ? OA1 : OA0));
        const bf16* sB = reinterpret_cast<const bf16*>(smem + (buf ? OB1 : OB0));

        #pragma unroll
        for (int kk = 0; kk < 64; kk += 16) {
            uint32_t af[4][4], bf_[8][2];
            #pragma unroll
            for (int mi = 0; mi < 4; mi++) {
                uint32_t a = cvta_s(&sA[(wm + mi * 16 + (lane & 15)) * 72 + kk + (lane >> 4) * 8]);
                ldsm_x4(af[mi], a);
            }
            #pragma unroll
            for (int p = 0; p < 4; p++) {
                uint32_t tmp[4];
                uint32_t a = cvta_s(&sB[(wn + p * 16 + (lane >> 4) * 8 + (lane & 7)) * 72 +
                                        kk + ((lane >> 3) & 1) * 8]);
                ldsm_x4(tmp, a);
                bf_[2 * p][0] = tmp[0]; bf_[2 * p][1] = tmp[1];
                bf_[2 * p + 1][0] = tmp[2]; bf_[2 * p + 1][1] = tmp[3];
            }
            #pragma unroll
            for (int mi = 0; mi < 4; mi++)
                #pragma unroll
                for (int ni = 0; ni < 8; ni++)
                    mma_bf16(acc[mi][ni], af[mi], bf_[ni]);
        }
        __syncthreads();

        if (ch + 2 < 32)
            out_issue_chunk(Vb, Pb, m0, n0, (ch + 2) * 64, sb, buf, tid);
    }

    const float g = gamma[0];
    #pragma unroll
    for (int mi = 0; mi < 4; mi++) {
        int grow = m0 + wm + mi * 16 + (lane >> 2);
        #pragma unroll
        for (int ni = 0; ni < 8; ni++) {
            int lc = wn + ni * 8 + (lane & 3) * 2;
            int gcol = n0 + lc;
            float2 iv = *reinterpret_cast<const float2*>(&sInv[lc]);
            size_t i0 = (size_t)b * C_ * T_ + (size_t)grow * T_ + gcol;
            size_t i1 = (size_t)b * C_ * T_ + (size_t)(grow + 8) * T_ + gcol;
            float2 x0 = *reinterpret_cast<const float2*>(&x[i0]);
            float2 x1 = *reinterpret_cast<const float2*>(&x[i1]);
            *reinterpret_cast<float2*>(&O[i0]) =
                make_float2(g * acc[mi][ni][0] * iv.x + x0.x, g * acc[mi][ni][1] * iv.y + x0.y);
            *reinterpret_cast<float2*>(&O[i1]) =
                make_float2(g * acc[mi][ni][2] * iv.x + x1.x, g * acc[mi][ni][3] * iv.y + x1.y);
        }
    }
}

// ---------------------------------------------------------------------------
// Launch
// ---------------------------------------------------------------------------
extern "C" void kernel_launch(void* const* d_in, const int* in_sizes, int n_in,
                              void* d_out, int out_size)
{
    const float* x     = (const float*)d_in[0];
    const float* wq    = (const float*)d_in[1];
    const float* bq    = (const float*)d_in[2];
    const float* wk    = (const float*)d_in[3];
    const float* bk    = (const float*)d_in[4];
    const float* wv    = (const float*)d_in[5];
    const float* bv    = (const float*)d_in[6];
    const float* gamma = (const float*)d_in[7];
    float* out = (float*)d_out;

    bf16 *xb, *wall, *qkv, *pb;
    float *ball, *rs;
    cudaGetSymbolAddress((void**)&xb,   g_xb);
    cudaGetSymbolAddress((void**)&wall, g_wall);
    cudaGetSymbolAddress((void**)&ball, g_ball);
    cudaGetSymbolAddress((void**)&qkv,  g_qkv);
    cudaGetSymbolAddress((void**)&pb,   g_p);
    cudaGetSymbolAddress((void**)&rs,   g_rs);

    cudaFuncSetAttribute(proj_stk,   cudaFuncAttributeMaxDynamicSharedMemorySize, PJ_SMEM);
    cudaFuncSetAttribute(score_exp4, cudaFuncAttributeMaxDynamicSharedMemorySize, SC_SMEM);
    cudaFuncSetAttribute(out_mma5,   cudaFuncAttributeMaxDynamicSharedMemorySize, OUT_SMEM);

    f2b_all<<<(NTOT + 255) / 256, 256>>>(x, xb, wq, wk, wv, wall, bq, bk, bv, ball);

    proj_stk<<<dim3(T_ / 128, MQKV / 128, B_), 256, PJ_SMEM>>>(wall, ball, xb, qkv);

    score_exp4<<<dim3(T_ / 256, T_ / 128, B_), 256, SC_SMEM>>>(qkv, pb, rs);

    out_mma5<<<dim3(T_ / 128, C_ / 128, B_), 128, OUT_SMEM>>>(qkv, pb, rs, x, gamma, out);
}